// round 14
// baseline (speedup 1.0000x reference)
#include <cuda_runtime.h>
#include <cuda_fp16.h>
#include <stdint.h>
#include <math.h>

// Problem constants
#define BB   4
#define TT   2048
#define DD   1024
#define HH   64
#define NSd  32
#define KK   8
#define HVd  32
#define NT   8192      // BB*TT tokens
#define NTS  65536     // NT*KK token-slots
#define QTILES 16      // 128-token tiles per head
#define LSTRIDE 2048   // per-head list stride
#define CC   64        // chunk length
#define NCH  32        // chunks per sequence
#define NCHUNKS 1024   // BB*KK*NCH

// ---------------- scratch (static device memory; no allocation) ----------------
__device__ float g_ra[NT * 128];
__device__ float g_rw[NTS];
__device__ float g_dsel[NTS];             // per-slot decay EXPONENT (<=0)
__device__ int   g_cursor[HH];
__device__ int   g_list[HH * LSTRIDE];
__device__ float g_qsel[NTS * 32];        // phase1 overwrites with qd = q*exp(L)
__device__ float g_ksel[NTS * 32];
__device__ float g_vsel[NTS * 32];
__device__ float g_yslot[NTS * 32];
__device__ float g_ysum[NT * 32];
__device__ float g_WoT[32 * DD];
__device__ float g_U[NCHUNKS * 1024];
__device__ float g_P63[NCHUNKS];
__device__ float g_Schunk[NCHUNKS * 1024];
// pre-converted fp16 operands (packed half2 words)
__device__ unsigned g_xh[NT * 512];           // x hi
__device__ unsigned g_xl[NT * 512];           // x lo (for gemm_ra 3-pass)
__device__ unsigned g_wh[HH * 96 * 512];      // W qkv hi
__device__ unsigned g_wl[HH * 96 * 512];      // W qkv lo
__device__ unsigned g_wrah[128 * 512];        // [Wr;Wa] hi
__device__ unsigned g_wral[128 * 512];        // [Wr;Wa] lo
__device__ float g_zero4[4] = {0.f, 0.f, 0.f, 0.f};

// ---------------- helpers ----------------
__device__ __forceinline__ float silu_f(float x) {
    return x / (1.0f + expf(-x));
}

__device__ __forceinline__ void f16_split2(float x0, float x1, unsigned& hi, unsigned& lo) {
    __half2 h2 = __floats2half2_rn(x0, x1);
    float h0 = __low2float(h2);
    float h1 = __high2float(h2);
    __half2 l2 = __floats2half2_rn(x0 - h0, x1 - h1);
    hi = *(unsigned*)&h2;
    lo = *(unsigned*)&l2;
}

__device__ __forceinline__ void mma_f16(float* c, const unsigned* a, const unsigned* b) {
    asm volatile(
        "mma.sync.aligned.m16n8k16.row.col.f32.f16.f16.f32 "
        "{%0,%1,%2,%3}, {%4,%5,%6,%7}, {%8,%9}, {%0,%1,%2,%3};"
        : "+f"(c[0]), "+f"(c[1]), "+f"(c[2]), "+f"(c[3])
        : "r"(a[0]), "r"(a[1]), "r"(a[2]), "r"(a[3]), "r"(b[0]), "r"(b[1]));
}

__device__ __forceinline__ void ldsm_x4(unsigned* r, uint32_t addr) {
    asm volatile("ldmatrix.sync.aligned.m8n8.x4.shared.b16 {%0,%1,%2,%3}, [%4];"
        : "=r"(r[0]), "=r"(r[1]), "=r"(r[2]), "=r"(r[3]) : "r"(addr));
}

#define CP_ASYNC16(dst, src) \
    asm volatile("cp.async.cg.shared.global [%0], [%1], 16;" :: "r"(dst), "l"(src) : "memory")
#define CP_COMMIT() asm volatile("cp.async.commit_group;" ::: "memory")
#define CP_WAIT1()  asm volatile("cp.async.wait_group 1;" ::: "memory")

// swizzled word index within a 16-word (64B) smem row
__device__ __forceinline__ int swz_word(int row, int kw) {
    return row * 16 + ((((kw >> 2) ^ ((row >> 1) & 3))) << 2) + (kw & 3);
}

__device__ __forceinline__ void split8_store(const float4 p0, const float4 p1,
                                             unsigned* dh, unsigned* dl) {
    uint4 oh, ol;
    unsigned hh_, ll_;
    f16_split2(p0.x, p0.y, hh_, ll_); oh.x = hh_; ol.x = ll_;
    f16_split2(p0.z, p0.w, hh_, ll_); oh.y = hh_; ol.y = ll_;
    f16_split2(p1.x, p1.y, hh_, ll_); oh.z = hh_; ol.z = ll_;
    f16_split2(p1.z, p1.w, hh_, ll_); oh.w = hh_; ol.w = ll_;
    *(uint4*)dh = oh;
    *(uint4*)dl = ol;
}

// ---------------- kernel: fused prep (WoT transpose, cursors, all fp16 conversions) ----------------
__global__ void prep_kernel(const float* __restrict__ Wo,
                            const float* __restrict__ x,
                            const float* __restrict__ Wq,
                            const float* __restrict__ Wk,
                            const float* __restrict__ Wv,
                            const float* __restrict__ Wr,
                            const float* __restrict__ Wa) {
    int blk = blockIdx.x;
    int tid = threadIdx.x;
    if (blk < 128) {
        int o = blk * 256 + tid;
        int v = o >> 10, d = o & 1023;
        g_WoT[o] = Wo[d * 32 + v];
        if (o < HH) g_cursor[o] = 0;
    } else if (blk < 4224) {
        int u = (blk - 128) * 256 + tid;            // (token, wordgrp)
        int tok = u >> 7, w4 = u & 127;
        const float* src = x + (size_t)tok * DD + w4 * 8;
        size_t base = (size_t)tok * 512 + w4 * 4;
        split8_store(*(const float4*)src, *(const float4*)(src + 4),
                     &g_xh[base], &g_xl[base]);
    } else if (blk < 7296) {
        int u = (blk - 4224) * 256 + tid;           // (h, row 0..95, wordgrp)
        int h = u / (96 * 128);
        int rem = u - h * 96 * 128;
        int r = rem >> 7, w4 = rem & 127;
        const float* src = (r < 32) ? (Wq + (size_t)(h * 32 + r) * DD)
                         : (r < 64) ? (Wk + (size_t)(h * 32 + r - 32) * DD)
                                    : (Wv + (size_t)(h * 32 + r - 64) * DD);
        src += w4 * 8;
        size_t base = ((size_t)h * 96 + r) * 512 + w4 * 4;
        split8_store(*(const float4*)src, *(const float4*)(src + 4),
                     &g_wh[base], &g_wl[base]);
    } else {
        int u = (blk - 7296) * 256 + tid;           // (row 0..127, wordgrp)
        int r = u >> 7, w4 = u & 127;
        const float* src = (r < 64) ? (Wr + (size_t)r * DD) : (Wa + (size_t)(r - 64) * DD);
        src += w4 * 8;
        size_t base = (size_t)r * 512 + w4 * 4;
        split8_store(*(const float4*)src, *(const float4*)(src + 4),
                     &g_wrah[base], &g_wral[base]);
    }
}

// ---------------- kernel: router + decay GEMM (fp16 3-pass, cp.async, BM=64) ----------------
#define RA_ST   24576
#define RA_XL   4096
#define RA_WH   8192
#define RA_WL   16384
__global__ void __launch_bounds__(256) gemm_ra_f16(const float* dummy) {
    __shared__ __align__(16) unsigned char sbuf[2 * RA_ST];
    int tid = threadIdx.x;
    int m0 = blockIdx.x * 64;
    uint32_t sb = (uint32_t)__cvta_generic_to_shared(sbuf);
    int w = tid >> 5, lane = tid & 31;
    int mw = w >> 2, nw = w & 3;
    int g = lane >> 2, tig = lane & 3;

    float acc[2][4][4];
#pragma unroll
    for (int mi = 0; mi < 2; mi++)
#pragma unroll
        for (int i = 0; i < 4; i++)
#pragma unroll
            for (int j = 0; j < 4; j++) acc[mi][i][j] = 0.0f;

#define RA_PRODUCE(stg, kt) do {                                                   \
        uint32_t stoff = sb + (stg) * RA_ST;                                       \
        int kw0 = (kt) * 16;                                                       \
        _Pragma("unroll")                                                          \
        for (int i = 0; i < 6; i++) {                                              \
            int u = tid + i * 256;                                                 \
            if (u < 256) {            /* X hi */                                   \
                int row = u >> 2, seg = u & 3;                                     \
                const void* src = (const void*)&g_xh[(size_t)(m0 + row) * 512 + kw0 + seg * 4]; \
                CP_ASYNC16(stoff + row * 64 + (((seg ^ ((row >> 1) & 3))) << 4), src); \
            } else if (u < 512) {     /* X lo */                                   \
                int v = u - 256; int row = v >> 2, seg = v & 3;                    \
                const void* src = (const void*)&g_xl[(size_t)(m0 + row) * 512 + kw0 + seg * 4]; \
                CP_ASYNC16(stoff + RA_XL + row * 64 + (((seg ^ ((row >> 1) & 3))) << 4), src); \
            } else if (u < 1024) {    /* W hi */                                   \
                int v = u - 512; int row = v >> 2, seg = v & 3;                    \
                const void* src = (const void*)&g_wrah[(size_t)row * 512 + kw0 + seg * 4]; \
                CP_ASYNC16(stoff + RA_WH + row * 64 + (((seg ^ ((row >> 1) & 3))) << 4), src); \
            } else {                  /* W lo */                                   \
                int v = u - 1024; int row = v >> 2, seg = v & 3;                   \
                const void* src = (const void*)&g_wral[(size_t)row * 512 + kw0 + seg * 4]; \
                CP_ASYNC16(stoff + RA_WL + row * 64 + (((seg ^ ((row >> 1) & 3))) << 4), src); \
            }                                                                      \
        }                                                                          \
    } while (0)

    RA_PRODUCE(0, 0);
    CP_COMMIT();

#pragma unroll 1
    for (int kt = 0; kt < 32; kt++) {
        int cur = kt & 1, nxt = cur ^ 1;
        if (kt + 1 < 32) RA_PRODUCE(nxt, kt + 1);
        CP_COMMIT();
        CP_WAIT1();
        __syncthreads();

        const unsigned* XH = (const unsigned*)(sbuf + cur * RA_ST);
        const unsigned* XL = (const unsigned*)(sbuf + cur * RA_ST + RA_XL);
        const unsigned* WH = (const unsigned*)(sbuf + cur * RA_ST + RA_WH);
        const unsigned* WL = (const unsigned*)(sbuf + cur * RA_ST + RA_WL);
#pragma unroll
        for (int ka = 0; ka < 2; ka++) {
            int kw = ka * 8 + tig;
            unsigned ahi[2][4], alo[2][4];
#pragma unroll
            for (int mi = 0; mi < 2; mi++) {
                int r0 = mw * 32 + mi * 16 + g;
                ahi[mi][0] = XH[swz_word(r0, kw)];
                ahi[mi][1] = XH[swz_word(r0 + 8, kw)];
                ahi[mi][2] = XH[swz_word(r0, kw + 4)];
                ahi[mi][3] = XH[swz_word(r0 + 8, kw + 4)];
                alo[mi][0] = XL[swz_word(r0, kw)];
                alo[mi][1] = XL[swz_word(r0 + 8, kw)];
                alo[mi][2] = XL[swz_word(r0, kw + 4)];
                alo[mi][3] = XL[swz_word(r0 + 8, kw + 4)];
            }
#pragma unroll
            for (int na = 0; na < 4; na++) {
                int col = nw * 32 + na * 8 + g;
                unsigned bhi[2], blo[2];
                bhi[0] = WH[swz_word(col, kw)];
                bhi[1] = WH[swz_word(col, kw + 4)];
                blo[0] = WL[swz_word(col, kw)];
                blo[1] = WL[swz_word(col, kw + 4)];
#pragma unroll
                for (int mi = 0; mi < 2; mi++) {
                    mma_f16(acc[mi][na], ahi[mi], bhi);
                    mma_f16(acc[mi][na], ahi[mi], blo);
                    mma_f16(acc[mi][na], alo[mi], bhi);
                }
            }
        }
        __syncthreads();
    }
#pragma unroll
    for (int mi = 0; mi < 2; mi++)
#pragma unroll
        for (int na = 0; na < 4; na++) {
            int col = nw * 32 + na * 8 + tig * 2;
            int row = m0 + mw * 32 + mi * 16 + g;
            *(float2*)&g_ra[(size_t)row * 128 + col]       = make_float2(acc[mi][na][0], acc[mi][na][1]);
            *(float2*)&g_ra[(size_t)(row + 8) * 128 + col] = make_float2(acc[mi][na][2], acc[mi][na][3]);
        }
#undef RA_PRODUCE
}

// ---------------- kernel: routing (top-8, rw, decay, direct list append) ----------------
__global__ void route_kernel(const float* __restrict__ A_log,
                             const float* __restrict__ dt_bias) {
    int lane = threadIdx.x & 31;
    int w = threadIdx.x >> 5;
    int tok0 = blockIdx.x * 16 + w * 2;

    float v0[2], v1[2];
    const float* ra0 = g_ra + (size_t)tok0 * 128;
    const float* ra1 = ra0 + 128;
    v0[0] = ra0[lane]; v1[0] = ra0[lane + 32];
    v0[1] = ra1[lane]; v1[1] = ra1[lane + 32];
    int i0 = lane, i1 = lane + 32;
    float topv[2][8]; int tophi[2][8];
#pragma unroll
    for (int it = 0; it < 8; it++) {
#pragma unroll
        for (int tt = 0; tt < 2; tt++) {
            float bv; int bi;
            if (v0[tt] > v1[tt] || (v0[tt] == v1[tt] && i0 < i1)) { bv = v0[tt]; bi = i0; }
            else                                                   { bv = v1[tt]; bi = i1; }
#pragma unroll
            for (int off = 16; off > 0; off >>= 1) {
                float ov = __shfl_xor_sync(0xffffffffu, bv, off);
                int   oi = __shfl_xor_sync(0xffffffffu, bi, off);
                if (ov > bv || (ov == bv && oi < bi)) { bv = ov; bi = oi; }
            }
            topv[tt][it] = bv; tophi[tt][it] = bi;
            if (bi == i0) v0[tt] = -INFINITY;
            if (bi == i1) v1[tt] = -INFINITY;
        }
    }
#pragma unroll
    for (int tt = 0; tt < 2; tt++) {
        float s = 0.0f;
#pragma unroll
        for (int j = 0; j < 8; j++) s += expf(topv[tt][j] - topv[tt][0]);

        float myv = 0.0f; int myh = 0;
#pragma unroll
        for (int it = 0; it < 8; it++)
            if (lane == it) { myv = topv[tt][it]; myh = tophi[tt][it]; }

        if (lane < 8) {
            const float* ra = (tt == 0) ? ra0 : ra1;
            float rw = expf(myv - topv[tt][0]) / s;
            float z = ra[64 + myh] + dt_bias[myh];
            float sp = (z > 20.0f) ? z : log1pf(expf(z));
            int e = (tok0 + tt) * 8 + lane;
            g_rw[e] = rw;
            g_dsel[e] = -expf(A_log[myh]) * sp;
            int pos = atomicAdd(&g_cursor[myh], 1);
            g_list[myh * LSTRIDE + pos] = e;
        }
    }
}

// ---------------- kernel: grouped q/k/v GEMM (fp16 2-pass, BM=128, ldmatrix) ----------------
#define ST_SZ 20480
#define WH_OFF 8192
#define WL_OFF 14336
__global__ void __launch_bounds__(256, 2) gemm_qkv_f16(const float* dummy) {
    __shared__ __align__(16) unsigned char sbuf[2 * ST_SZ];
    __shared__ int s_ent[128];
    float* Cs = (float*)sbuf;

    int tid = threadIdx.x;
    int h = blockIdx.y;
    int cnt = g_cursor[h];
    int t0 = blockIdx.x * 128;
    if (t0 >= cnt) return;
    if (tid < 128) s_ent[tid] = (t0 + tid < cnt) ? g_list[h * LSTRIDE + t0 + tid] : -1;
    __syncthreads();

    uint32_t sb = (uint32_t)__cvta_generic_to_shared(sbuf);
    int w = tid >> 5, lane = tid & 31;
    int mw = w >> 1, nw = w & 1;
    int g = lane >> 2, tig = lane & 3;

    float acc[2][6][4];
#pragma unroll
    for (int mi = 0; mi < 2; mi++)
#pragma unroll
        for (int i = 0; i < 6; i++)
#pragma unroll
            for (int j = 0; j < 4; j++) acc[mi][i][j] = 0.0f;

    // ldmatrix per-lane byte offsets (within a stage)
    // A: fragment a0..a3 for rows mw*32+mi*16..; lane -> row r0+(l&15), chunk bit l>>4
    int arow = mw * 32 + (lane & 15);
    int acb  = (lane >> 4) & 1;
    int as_  = (arow >> 1) & 3;
    uint32_t offA0 = (uint32_t)(arow * 64 + ((acb ^ as_) << 4));          // ka=0 chunks {0,1}
    uint32_t offA1 = (uint32_t)(arow * 64 + (((2 | acb) ^ as_) << 4));    // ka=1 chunks {2,3}
    // B: pair p covers na=2p,2p+1; lane -> col base+(l&7)+((l>>4)<<3), chunk bit (l>>3)&1
    int bcol = nw * 48 + (lane & 7) + ((lane >> 4) << 3);
    int bcb  = (lane >> 3) & 1;
    int bs_  = (bcol >> 1) & 3;
    uint32_t offB0 = (uint32_t)(bcol * 64 + ((bcb ^ bs_) << 4));
    uint32_t offB1 = (uint32_t)(bcol * 64 + (((2 | bcb) ^ bs_) << 4));

    int xu0 = tid, xu1 = tid + 256;
    size_t whbase = (size_t)h * 96 * 512;

#define PRODUCE(stg, kt) do {                                                     \
        uint32_t stoff = sb + (stg) * ST_SZ;                                      \
        int kw0 = (kt) * 16;                                                      \
        { int u = xu0; int row = u >> 2, seg = u & 3;                             \
          int e = s_ent[row];                                                     \
          const void* src = (e >= 0) ? (const void*)&g_xh[(size_t)(e >> 3) * 512 + kw0 + seg * 4] \
                                     : (const void*)g_zero4;                      \
          CP_ASYNC16(stoff + row * 64 + (((seg ^ ((row >> 1) & 3))) << 4), src); } \
        { int u = xu1; int row = u >> 2, seg = u & 3;                             \
          int e = s_ent[row];                                                     \
          const void* src = (e >= 0) ? (const void*)&g_xh[(size_t)(e >> 3) * 512 + kw0 + seg * 4] \
                                     : (const void*)g_zero4;                      \
          CP_ASYNC16(stoff + row * 64 + (((seg ^ ((row >> 1) & 3))) << 4), src); } \
        _Pragma("unroll")                                                         \
        for (int i = 0; i < 3; i++) {                                             \
            int u = tid + i * 256;                                                \
            int hl = (u >= 384);                                                  \
            int v = hl ? (u - 384) : u;                                           \
            int row = v >> 2, seg = v & 3;                                        \
            const unsigned* gsrc = hl ? g_wl : g_wh;                              \
            const void* src = (const void*)&gsrc[whbase + (size_t)row * 512 + kw0 + seg * 4]; \
            uint32_t doff = stoff + (hl ? WL_OFF : WH_OFF) + row * 64             \
                            + (((seg ^ ((row >> 1) & 3))) << 4);                  \
            CP_ASYNC16(doff, src);                                                \
        }                                                                         \
    } while (0)

    PRODUCE(0, 0);
    CP_COMMIT();

#pragma unroll 1
    for (int kt = 0; kt < 32; kt++) {
        int cur = kt & 1, nxt = cur ^ 1;
        if (kt + 1 < 32) PRODUCE(nxt, kt + 1);
        CP_COMMIT();
        CP_WAIT1();
        __syncthreads();

        uint32_t stX  = sb + cur * ST_SZ;
        uint32_t stWH = stX + WH_OFF;
        uint32_t stWL = stX + WL_OFF;
#pragma unroll
        for (int ka = 0; ka < 2; ka++) {
            uint32_t aoff = (ka == 0) ? offA0 : offA1;
            uint32_t boff = (ka == 0) ? offB0 : offB1;
            unsigned ahi0[4], ahi1[4];
            ldsm_x4(ahi0, stX + aoff);           // mi = 0 (rows mw*32 .. +15)
            ldsm_x4(ahi1, stX + aoff + 1024);    // mi = 1 (rows +16)
#pragma unroll
            for (int p = 0; p < 3; p++) {
                unsigned bh[4], bl[4];
                ldsm_x4(bh, stWH + boff + p * 1024);
                ldsm_x4(bl, stWL + boff + p * 1024);
                // na = 2p   -> bh[0..1], bl[0..1]
                mma_f16(acc[0][2 * p],     ahi0, bh);
                mma_f16(acc[0][2 * p],     ahi0, bl);
                mma_f16(acc[1][2 * p],     ahi1, bh);
                mma_f16(acc[1][2 * p],     ahi1, bl);
                // na = 2p+1 -> bh[2..3], bl[2..3]
                mma_f16(acc[0][2 * p + 1], ahi0, bh + 2);
                mma_f16(acc[0][2 * p + 1], ahi0, bl + 2);
                mma_f16(acc[1][2 * p + 1], ahi1, bh + 2);
                mma_f16(acc[1][2 * p + 1], ahi1, bl + 2);
            }
        }
        __syncthreads();
    }

#pragma unroll 1
    for (int half = 0; half < 2; half++) {
        if ((mw >> 1) == half) {
#pragma unroll
            for (int mi = 0; mi < 2; mi++)
#pragma unroll
                for (int na = 0; na < 6; na++) {
                    int col = nw * 48 + na * 8 + tig * 2;
                    int row = mw * 32 + mi * 16 + g - half * 64;
                    Cs[row * 97 + col]           = acc[mi][na][0];
                    Cs[row * 97 + col + 1]       = acc[mi][na][1];
                    Cs[(row + 8) * 97 + col]     = acc[mi][na][2];
                    Cs[(row + 8) * 97 + col + 1] = acc[mi][na][3];
                }
        }
        __syncthreads();
#pragma unroll 1
        for (int rep = 0; rep < 8; rep++) {
            int r = rep * 8 + w;
            int e = s_ent[half * 64 + r];
            if (e < 0) continue;
            float wr = g_rw[e];
            float qv = Cs[r * 97 + lane];
            float qs = silu_f(qv);
            float ssq = qs * qs;
#pragma unroll
            for (int o = 16; o > 0; o >>= 1) ssq += __shfl_xor_sync(0xffffffffu, ssq, o);
            g_qsel[(size_t)e * 32 + lane] = qs * rsqrtf(ssq + 1e-6f) * wr;
            float kv = Cs[r * 97 + 32 + lane];
            float ks = silu_f(kv);
            float ssk = ks * ks;
#pragma unroll
            for (int o = 16; o > 0; o >>= 1) ssk += __shfl_xor_sync(0xffffffffu, ssk, o);
            g_ksel[(size_t)e * 32 + lane] = ks * rsqrtf(ssk + 1e-6f);
            float vv = Cs[r * 97 + 64 + lane];
            g_vsel[(size_t)e * 32 + lane] = silu_f(vv);
        }
        __syncthreads();
    }
#undef PRODUCE
}

// ---------------- kernel: chunked scan phase 1 (intra-chunk, vectorized) ----------------
__global__ void chunk_intra() {
    __shared__ float qs[64][36], vs[64][36];
    __shared__ float ksT[32][68];
    __shared__ float As[64][65];
    __shared__ float Ls[64], rr[64];
    int tid = threadIdx.x;
    int cid = blockIdx.x;
    int b = cid >> 8, kk = (cid >> 5) & 7, c = cid & 31;
    size_t e0 = ((size_t)(b * TT + c * CC)) * KK + kk;

#pragma unroll
    for (int it = 0; it < 2; it++) {
        int i = (tid >> 3) + it * 32;
        int c4 = (tid & 7) * 4;
        size_t gidx = (e0 + (size_t)i * KK) * 32 + c4;
        float4 qv = *(const float4*)&g_qsel[gidx];
        float4 kv = *(const float4*)&g_ksel[gidx];
        float4 vv = *(const float4*)&g_vsel[gidx];
        qs[i][c4] = qv.x; qs[i][c4+1] = qv.y; qs[i][c4+2] = qv.z; qs[i][c4+3] = qv.w;
        vs[i][c4] = vv.x; vs[i][c4+1] = vv.y; vs[i][c4+2] = vv.z; vs[i][c4+3] = vv.w;
        ksT[c4+0][i] = kv.x; ksT[c4+1][i] = kv.y; ksT[c4+2][i] = kv.z; ksT[c4+3][i] = kv.w;
    }
    if (tid < 64) Ls[tid] = g_dsel[e0 + (size_t)tid * KK];
    __syncthreads();
    if (tid == 0) {
        float a = 0.0f;
        for (int i = 0; i < 64; i++) { a += Ls[i]; Ls[i] = a; }
    }
    __syncthreads();
    if (tid < 64) rr[tid] = __expf(Ls[63] - Ls[tid]);

    {
        int i = tid >> 2, s0 = (tid & 3) * 16;
        float acc[16];
#pragma unroll
        for (int j = 0; j < 16; j++) acc[j] = 0.0f;
#pragma unroll 4
        for (int n = 0; n < 32; n++) {
            float qv = qs[i][n];
            float4 k0_ = *(const float4*)&ksT[n][s0];
            float4 k1_ = *(const float4*)&ksT[n][s0 + 4];
            float4 k2_ = *(const float4*)&ksT[n][s0 + 8];
            float4 k3_ = *(const float4*)&ksT[n][s0 + 12];
            acc[0]  = fmaf(qv, k0_.x, acc[0]);  acc[1]  = fmaf(qv, k0_.y, acc[1]);
            acc[2]  = fmaf(qv, k0_.z, acc[2]);  acc[3]  = fmaf(qv, k0_.w, acc[3]);
            acc[4]  = fmaf(qv, k1_.x, acc[4]);  acc[5]  = fmaf(qv, k1_.y, acc[5]);
            acc[6]  = fmaf(qv, k1_.z, acc[6]);  acc[7]  = fmaf(qv, k1_.w, acc[7]);
            acc[8]  = fmaf(qv, k2_.x, acc[8]);  acc[9]  = fmaf(qv, k2_.y, acc[9]);
            acc[10] = fmaf(qv, k2_.z, acc[10]); acc[11] = fmaf(qv, k2_.w, acc[11]);
            acc[12] = fmaf(qv, k3_.x, acc[12]); acc[13] = fmaf(qv, k3_.y, acc[13]);
            acc[14] = fmaf(qv, k3_.z, acc[14]); acc[15] = fmaf(qv, k3_.w, acc[15]);
        }
        float Li = Ls[i];
#pragma unroll
        for (int j = 0; j < 16; j++) {
            int s = s0 + j;
            As[i][s] = (s <= i) ? acc[j] * __expf(Li - Ls[s]) : 0.0f;
        }
        int cg = (tid & 3) * 8;
        float ei = __expf(Li);
        size_t gq = (e0 + (size_t)i * KK) * 32 + cg;
#pragma unroll
        for (int j = 0; j < 8; j++)
            g_qsel[gq + j] = qs[i][cg + j] * ei;
    }
    __syncthreads();

    {
        int i = tid >> 2, vg = (tid & 3) * 8;
        float y[8];
#pragma unroll
        for (int j = 0; j < 8; j++) y[j] = 0.0f;
#pragma unroll 4
        for (int s = 0; s < 64; s++) {
            float a = As[i][s];
            float4 v0 = *(const float4*)&vs[s][vg];
            float4 v1 = *(const float4*)&vs[s][vg + 4];
            y[0] = fmaf(a, v0.x, y[0]); y[1] = fmaf(a, v0.y, y[1]);
            y[2] = fmaf(a, v0.z, y[2]); y[3] = fmaf(a, v0.w, y[3]);
            y[4] = fmaf(a, v1.x, y[4]); y[5] = fmaf(a, v1.y, y[5]);
            y[6] = fmaf(a, v1.z, y[6]); y[7] = fmaf(a, v1.w, y[7]);
        }
        size_t gy = (e0 + (size_t)i * KK) * 32 + vg;
        *(float4*)&g_yslot[gy]     = make_float4(y[0], y[1], y[2], y[3]);
        *(float4*)&g_yslot[gy + 4] = make_float4(y[4], y[5], y[6], y[7]);
    }

    {
        int n = tid >> 3, vg = (tid & 7) * 4;
        float u[4] = {0.f, 0.f, 0.f, 0.f};
#pragma unroll 4
        for (int s = 0; s < 64; s++) {
            float kd = ksT[n][s] * rr[s];
            float4 vv = *(const float4*)&vs[s][vg];
            u[0] = fmaf(kd, vv.x, u[0]); u[1] = fmaf(kd, vv.y, u[1]);
            u[2] = fmaf(kd, vv.z, u[2]); u[3] = fmaf(kd, vv.w, u[3]);
        }
        *(float4*)&g_U[(size_t)cid * 1024 + n * 32 + vg] = make_float4(u[0], u[1], u[2], u[3]);
    }
    if (tid == 0) g_P63[cid] = __expf(Ls[63]);
}

// ---------------- kernel: chunked scan phase 2 (state propagation) ----------------
__global__ void chunk_state(const float* __restrict__ S0,
                            float* __restrict__ sfin) {
    int tid = threadIdx.x;
    int seq = blockIdx.x;
    float S = S0[(size_t)seq * 1024 + tid];
#pragma unroll 1
    for (int c = 0; c < NCH; c++) {
        int cid = seq * NCH + c;
        g_Schunk[(size_t)cid * 1024 + tid] = S;
        float P = g_P63[cid];
        S = fmaf(P, S, g_U[(size_t)cid * 1024 + tid]);
    }
    if (sfin) sfin[(size_t)seq * 1024 + tid] = S;
}

// ---------------- kernel: chunked scan phase 3 (cross-chunk term) ----------------
__global__ void chunk_cross() {
    __shared__ float Sc[1024];
    __shared__ float qds[64][33];
    int tid = threadIdx.x;
    int cid = blockIdx.x;
    int b = cid >> 8, kk = (cid >> 5) & 7, c = cid & 31;
    size_t e0 = ((size_t)(b * TT + c * CC)) * KK + kk;

    {
        float4 s4 = *(const float4*)&g_Schunk[(size_t)cid * 1024 + tid * 4];
        *(float4*)&Sc[tid * 4] = s4;
    }
#pragma unroll
    for (int it = 0; it < 2; it++) {
        int i = (tid >> 3) + it * 32;
        int c4 = (tid & 7) * 4;
        float4 qv = *(const float4*)&g_qsel[(e0 + (size_t)i * KK) * 32 + c4];
        qds[i][c4] = qv.x; qds[i][c4+1] = qv.y; qds[i][c4+2] = qv.z; qds[i][c4+3] = qv.w;
    }
    __syncthreads();

    int i = tid >> 2, vg = (tid & 3) * 8;
    size_t gy = (e0 + (size_t)i * KK) * 32 + vg;
    float4 y0 = *(const float4*)&g_yslot[gy];
    float4 y1 = *(const float4*)&g_yslot[gy + 4];
    float y[8] = {y0.x, y0.y, y0.z, y0.w, y1.x, y1.y, y1.z, y1.w};
#pragma unroll 8
    for (int n = 0; n < 32; n++) {
        float qv = qds[i][n];
#pragma unroll
        for (int j = 0; j < 8; j++)
            y[j] = fmaf(qv, Sc[n * 32 + vg + j], y[j]);
    }
    *(float4*)&g_yslot[gy]     = make_float4(y[0], y[1], y[2], y[3]);
    *(float4*)&g_yslot[gy + 4] = make_float4(y[4], y[5], y[6], y[7]);
}

// ---------------- kernel: slot reduce -> g_ysum ----------------
__global__ void ysum_kernel() {
    int u = blockIdx.x * 256 + threadIdx.x;
    int t = u >> 5, v = u & 31;
    float s = 0.0f;
    size_t p = (size_t)t * KK * 32 + v;
#pragma unroll
    for (int kk = 0; kk < KK; kk++) s += g_yslot[p + kk * 32];
    g_ysum[u] = s;
}

// ---------------- kernel: output projection ----------------
__global__ void outproj_kernel(float* __restrict__ out) {
    __shared__ float ysum[32][32];
    int tid = threadIdx.x;
    int tok0 = blockIdx.x * 32;
    int d = blockIdx.y * 256 + tid;

#pragma unroll
    for (int u = tid; u < 1024; u += 256) {
        int tk = u >> 5, v = u & 31;
        ysum[tk][v] = g_ysum[(size_t)(tok0) * 32 + u];
    }
    __syncthreads();

    float wreg[32];
#pragma unroll
    for (int vv = 0; vv < 32; vv++) wreg[vv] = g_WoT[vv * DD + d];

#pragma unroll 4
    for (int tk = 0; tk < 32; tk++) {
        float acc = 0.0f;
#pragma unroll
        for (int vv = 0; vv < 32; vv += 4) {
            float4 y4 = *(const float4*)&ysum[tk][vv];
            acc = fmaf(wreg[vv],     y4.x, acc);
            acc = fmaf(wreg[vv + 1], y4.y, acc);
            acc = fmaf(wreg[vv + 2], y4.z, acc);
            acc = fmaf(wreg[vv + 3], y4.w, acc);
        }
        out[(size_t)(tok0 + tk) * DD + d] = acc;
    }
}

// ---------------- launch ----------------
extern "C" void kernel_launch(void* const* d_in, const int* in_sizes, int n_in,
                              void* d_out, int out_size) {
    const float* x       = (const float*)d_in[0];
    const float* Wr      = (const float*)d_in[1];
    const float* Wq      = (const float*)d_in[2];
    const float* Wk      = (const float*)d_in[3];
    const float* Wv      = (const float*)d_in[4];
    const float* Wa      = (const float*)d_in[5];
    const float* A_log   = (const float*)d_in[6];
    const float* dt_bias = (const float*)d_in[7];
    const float* Wo      = (const float*)d_in[8];
    const float* S0      = (const float*)d_in[9];
    float* out = (float*)d_out;

    const long y_elems = (long)NT * DD;
    const long s_elems = (long)BB * KK * NSd * HVd;
    float* sfin = ((long)out_size >= y_elems + s_elems) ? (out + y_elems) : nullptr;

    prep_kernel<<<7360, 256>>>(Wo, x, Wq, Wk, Wv, Wr, Wa);
    gemm_ra_f16<<<NT / 64, 256>>>(nullptr);
    route_kernel<<<NT / 16, 256>>>(A_log, dt_bias);
    gemm_qkv_f16<<<dim3(QTILES, HH), 256>>>(nullptr);
    chunk_intra<<<NCHUNKS, 256>>>();
    chunk_state<<<BB * KK, 1024>>>(S0, sfin);
    chunk_cross<<<NCHUNKS, 256>>>();
    ysum_kernel<<<NT * 32 / 256, 256>>>();
    outproj_kernel<<<dim3(NT / 32, 4), 256>>>(out);
}

// round 15
// speedup vs baseline: 1.0061x; 1.0061x over previous
#include <cuda_runtime.h>
#include <cuda_fp16.h>
#include <stdint.h>
#include <math.h>

// Problem constants
#define BB   4
#define TT   2048
#define DD   1024
#define HH   64
#define NSd  32
#define KK   8
#define HVd  32
#define NT   8192      // BB*TT tokens
#define NTS  65536     // NT*KK token-slots
#define QTILES 16      // 128-token tiles per head
#define LSTRIDE 2048   // per-head list stride
#define CC   64        // chunk length
#define NCH  32        // chunks per sequence
#define NCHUNKS 1024   // BB*KK*NCH

// ---------------- scratch (static device memory; no allocation) ----------------
__device__ float g_ra[NT * 128];
__device__ float g_rw[NTS];
__device__ float g_dsel[NTS];             // per-slot decay EXPONENT (<=0)
__device__ int   g_cursor[HH];
__device__ int   g_list[HH * LSTRIDE];
__device__ float g_qsel[NTS * 32];        // phase1 overwrites with qd = q*exp(L)
__device__ float g_ksel[NTS * 32];
__device__ float g_vsel[NTS * 32];
__device__ float g_yslot[NTS * 32];
__device__ float g_ysum[NT * 32];
__device__ float g_WoT[32 * DD];
__device__ float g_U[NCHUNKS * 1024];
__device__ float g_P63[NCHUNKS];
__device__ float g_Schunk[NCHUNKS * 1024];
// pre-converted fp16 operands (packed half2 words)
__device__ unsigned g_xh[NT * 512];           // x hi
__device__ unsigned g_xl[NT * 512];           // x lo (for gemm_ra 3-pass)
__device__ unsigned g_wh[HH * 96 * 512];      // W qkv hi
__device__ unsigned g_wl[HH * 96 * 512];      // W qkv lo
__device__ unsigned g_wrah[128 * 512];        // [Wr;Wa] hi
__device__ unsigned g_wral[128 * 512];        // [Wr;Wa] lo
__device__ float g_zero4[4] = {0.f, 0.f, 0.f, 0.f};

// ---------------- helpers ----------------
__device__ __forceinline__ float silu_f(float x) {
    return x / (1.0f + expf(-x));
}

__device__ __forceinline__ void f16_split2(float x0, float x1, unsigned& hi, unsigned& lo) {
    __half2 h2 = __floats2half2_rn(x0, x1);
    float h0 = __low2float(h2);
    float h1 = __high2float(h2);
    __half2 l2 = __floats2half2_rn(x0 - h0, x1 - h1);
    hi = *(unsigned*)&h2;
    lo = *(unsigned*)&l2;
}

__device__ __forceinline__ void mma_f16(float* c, const unsigned* a, const unsigned* b) {
    asm volatile(
        "mma.sync.aligned.m16n8k16.row.col.f32.f16.f16.f32 "
        "{%0,%1,%2,%3}, {%4,%5,%6,%7}, {%8,%9}, {%0,%1,%2,%3};"
        : "+f"(c[0]), "+f"(c[1]), "+f"(c[2]), "+f"(c[3])
        : "r"(a[0]), "r"(a[1]), "r"(a[2]), "r"(a[3]), "r"(b[0]), "r"(b[1]));
}

__device__ __forceinline__ void ldsm_x4(unsigned* r, uint32_t addr) {
    asm volatile("ldmatrix.sync.aligned.m8n8.x4.shared.b16 {%0,%1,%2,%3}, [%4];"
        : "=r"(r[0]), "=r"(r[1]), "=r"(r[2]), "=r"(r[3]) : "r"(addr));
}

#define CP_ASYNC16(dst, src) \
    asm volatile("cp.async.cg.shared.global [%0], [%1], 16;" :: "r"(dst), "l"(src) : "memory")
#define CP_COMMIT() asm volatile("cp.async.commit_group;" ::: "memory")
#define CP_WAIT1()  asm volatile("cp.async.wait_group 1;" ::: "memory")

// swizzled word index within a 16-word (64B) smem row
__device__ __forceinline__ int swz_word(int row, int kw) {
    return row * 16 + ((((kw >> 2) ^ ((row >> 1) & 3))) << 2) + (kw & 3);
}

__device__ __forceinline__ void split8_store(const float4 p0, const float4 p1,
                                             unsigned* dh, unsigned* dl) {
    uint4 oh, ol;
    unsigned hh_, ll_;
    f16_split2(p0.x, p0.y, hh_, ll_); oh.x = hh_; ol.x = ll_;
    f16_split2(p0.z, p0.w, hh_, ll_); oh.y = hh_; ol.y = ll_;
    f16_split2(p1.x, p1.y, hh_, ll_); oh.z = hh_; ol.z = ll_;
    f16_split2(p1.z, p1.w, hh_, ll_); oh.w = hh_; ol.w = ll_;
    *(uint4*)dh = oh;
    *(uint4*)dl = ol;
}

// ---------------- kernel: fused prep (WoT transpose, cursors, all fp16 conversions) ----------------
__global__ void prep_kernel(const float* __restrict__ Wo,
                            const float* __restrict__ x,
                            const float* __restrict__ Wq,
                            const float* __restrict__ Wk,
                            const float* __restrict__ Wv,
                            const float* __restrict__ Wr,
                            const float* __restrict__ Wa) {
    int blk = blockIdx.x;
    int tid = threadIdx.x;
    if (blk < 128) {
        int o = blk * 256 + tid;
        int v = o >> 10, d = o & 1023;
        g_WoT[o] = Wo[d * 32 + v];
        if (o < HH) g_cursor[o] = 0;
    } else if (blk < 4224) {
        int u = (blk - 128) * 256 + tid;            // (token, wordgrp)
        int tok = u >> 7, w4 = u & 127;
        const float* src = x + (size_t)tok * DD + w4 * 8;
        size_t base = (size_t)tok * 512 + w4 * 4;
        split8_store(*(const float4*)src, *(const float4*)(src + 4),
                     &g_xh[base], &g_xl[base]);
    } else if (blk < 7296) {
        int u = (blk - 4224) * 256 + tid;           // (h, row 0..95, wordgrp)
        int h = u / (96 * 128);
        int rem = u - h * 96 * 128;
        int r = rem >> 7, w4 = rem & 127;
        const float* src = (r < 32) ? (Wq + (size_t)(h * 32 + r) * DD)
                         : (r < 64) ? (Wk + (size_t)(h * 32 + r - 32) * DD)
                                    : (Wv + (size_t)(h * 32 + r - 64) * DD);
        src += w4 * 8;
        size_t base = ((size_t)h * 96 + r) * 512 + w4 * 4;
        split8_store(*(const float4*)src, *(const float4*)(src + 4),
                     &g_wh[base], &g_wl[base]);
    } else {
        int u = (blk - 7296) * 256 + tid;           // (row 0..127, wordgrp)
        int r = u >> 7, w4 = u & 127;
        const float* src = (r < 64) ? (Wr + (size_t)r * DD) : (Wa + (size_t)(r - 64) * DD);
        src += w4 * 8;
        size_t base = (size_t)r * 512 + w4 * 4;
        split8_store(*(const float4*)src, *(const float4*)(src + 4),
                     &g_wrah[base], &g_wral[base]);
    }
}

// ---------------- kernel: router + decay GEMM (fp16 3-pass, cp.async, BM=64) ----------------
#define RA_ST   24576
#define RA_XL   4096
#define RA_WH   8192
#define RA_WL   16384
__global__ void __launch_bounds__(256) gemm_ra_f16(const float* dummy) {
    __shared__ __align__(16) unsigned char sbuf[2 * RA_ST];
    int tid = threadIdx.x;
    int m0 = blockIdx.x * 64;
    uint32_t sb = (uint32_t)__cvta_generic_to_shared(sbuf);
    int w = tid >> 5, lane = tid & 31;
    int mw = w >> 2, nw = w & 3;
    int g = lane >> 2, tig = lane & 3;

    float acc[2][4][4];
#pragma unroll
    for (int mi = 0; mi < 2; mi++)
#pragma unroll
        for (int i = 0; i < 4; i++)
#pragma unroll
            for (int j = 0; j < 4; j++) acc[mi][i][j] = 0.0f;

#define RA_PRODUCE(stg, kt) do {                                                   \
        uint32_t stoff = sb + (stg) * RA_ST;                                       \
        int kw0 = (kt) * 16;                                                       \
        _Pragma("unroll")                                                          \
        for (int i = 0; i < 6; i++) {                                              \
            int u = tid + i * 256;                                                 \
            if (u < 256) {            /* X hi */                                   \
                int row = u >> 2, seg = u & 3;                                     \
                const void* src = (const void*)&g_xh[(size_t)(m0 + row) * 512 + kw0 + seg * 4]; \
                CP_ASYNC16(stoff + row * 64 + (((seg ^ ((row >> 1) & 3))) << 4), src); \
            } else if (u < 512) {     /* X lo */                                   \
                int v = u - 256; int row = v >> 2, seg = v & 3;                    \
                const void* src = (const void*)&g_xl[(size_t)(m0 + row) * 512 + kw0 + seg * 4]; \
                CP_ASYNC16(stoff + RA_XL + row * 64 + (((seg ^ ((row >> 1) & 3))) << 4), src); \
            } else if (u < 1024) {    /* W hi */                                   \
                int v = u - 512; int row = v >> 2, seg = v & 3;                    \
                const void* src = (const void*)&g_wrah[(size_t)row * 512 + kw0 + seg * 4]; \
                CP_ASYNC16(stoff + RA_WH + row * 64 + (((seg ^ ((row >> 1) & 3))) << 4), src); \
            } else {                  /* W lo */                                   \
                int v = u - 1024; int row = v >> 2, seg = v & 3;                   \
                const void* src = (const void*)&g_wral[(size_t)row * 512 + kw0 + seg * 4]; \
                CP_ASYNC16(stoff + RA_WL + row * 64 + (((seg ^ ((row >> 1) & 3))) << 4), src); \
            }                                                                      \
        }                                                                          \
    } while (0)

    RA_PRODUCE(0, 0);
    CP_COMMIT();

#pragma unroll 1
    for (int kt = 0; kt < 32; kt++) {
        int cur = kt & 1, nxt = cur ^ 1;
        if (kt + 1 < 32) RA_PRODUCE(nxt, kt + 1);
        CP_COMMIT();
        CP_WAIT1();
        __syncthreads();

        const unsigned* XH = (const unsigned*)(sbuf + cur * RA_ST);
        const unsigned* XL = (const unsigned*)(sbuf + cur * RA_ST + RA_XL);
        const unsigned* WH = (const unsigned*)(sbuf + cur * RA_ST + RA_WH);
        const unsigned* WL = (const unsigned*)(sbuf + cur * RA_ST + RA_WL);
#pragma unroll
        for (int ka = 0; ka < 2; ka++) {
            int kw = ka * 8 + tig;
            unsigned ahi[2][4], alo[2][4];
#pragma unroll
            for (int mi = 0; mi < 2; mi++) {
                int r0 = mw * 32 + mi * 16 + g;
                ahi[mi][0] = XH[swz_word(r0, kw)];
                ahi[mi][1] = XH[swz_word(r0 + 8, kw)];
                ahi[mi][2] = XH[swz_word(r0, kw + 4)];
                ahi[mi][3] = XH[swz_word(r0 + 8, kw + 4)];
                alo[mi][0] = XL[swz_word(r0, kw)];
                alo[mi][1] = XL[swz_word(r0 + 8, kw)];
                alo[mi][2] = XL[swz_word(r0, kw + 4)];
                alo[mi][3] = XL[swz_word(r0 + 8, kw + 4)];
            }
#pragma unroll
            for (int na = 0; na < 4; na++) {
                int col = nw * 32 + na * 8 + g;
                unsigned bhi[2], blo[2];
                bhi[0] = WH[swz_word(col, kw)];
                bhi[1] = WH[swz_word(col, kw + 4)];
                blo[0] = WL[swz_word(col, kw)];
                blo[1] = WL[swz_word(col, kw + 4)];
#pragma unroll
                for (int mi = 0; mi < 2; mi++) {
                    mma_f16(acc[mi][na], ahi[mi], bhi);
                    mma_f16(acc[mi][na], ahi[mi], blo);
                    mma_f16(acc[mi][na], alo[mi], bhi);
                }
            }
        }
        __syncthreads();
    }
#pragma unroll
    for (int mi = 0; mi < 2; mi++)
#pragma unroll
        for (int na = 0; na < 4; na++) {
            int col = nw * 32 + na * 8 + tig * 2;
            int row = m0 + mw * 32 + mi * 16 + g;
            *(float2*)&g_ra[(size_t)row * 128 + col]       = make_float2(acc[mi][na][0], acc[mi][na][1]);
            *(float2*)&g_ra[(size_t)(row + 8) * 128 + col] = make_float2(acc[mi][na][2], acc[mi][na][3]);
        }
#undef RA_PRODUCE
}

// ---------------- kernel: routing (top-8, rw, decay, direct list append) ----------------
__global__ void route_kernel(const float* __restrict__ A_log,
                             const float* __restrict__ dt_bias) {
    int lane = threadIdx.x & 31;
    int w = threadIdx.x >> 5;
    int tok0 = blockIdx.x * 16 + w * 2;

    float v0[2], v1[2];
    const float* ra0 = g_ra + (size_t)tok0 * 128;
    const float* ra1 = ra0 + 128;
    v0[0] = ra0[lane]; v1[0] = ra0[lane + 32];
    v0[1] = ra1[lane]; v1[1] = ra1[lane + 32];
    int i0 = lane, i1 = lane + 32;
    float topv[2][8]; int tophi[2][8];
#pragma unroll
    for (int it = 0; it < 8; it++) {
#pragma unroll
        for (int tt = 0; tt < 2; tt++) {
            float bv; int bi;
            if (v0[tt] > v1[tt] || (v0[tt] == v1[tt] && i0 < i1)) { bv = v0[tt]; bi = i0; }
            else                                                   { bv = v1[tt]; bi = i1; }
#pragma unroll
            for (int off = 16; off > 0; off >>= 1) {
                float ov = __shfl_xor_sync(0xffffffffu, bv, off);
                int   oi = __shfl_xor_sync(0xffffffffu, bi, off);
                if (ov > bv || (ov == bv && oi < bi)) { bv = ov; bi = oi; }
            }
            topv[tt][it] = bv; tophi[tt][it] = bi;
            if (bi == i0) v0[tt] = -INFINITY;
            if (bi == i1) v1[tt] = -INFINITY;
        }
    }
#pragma unroll
    for (int tt = 0; tt < 2; tt++) {
        float s = 0.0f;
#pragma unroll
        for (int j = 0; j < 8; j++) s += expf(topv[tt][j] - topv[tt][0]);

        float myv = 0.0f; int myh = 0;
#pragma unroll
        for (int it = 0; it < 8; it++)
            if (lane == it) { myv = topv[tt][it]; myh = tophi[tt][it]; }

        if (lane < 8) {
            const float* ra = (tt == 0) ? ra0 : ra1;
            float rw = expf(myv - topv[tt][0]) / s;
            float z = ra[64 + myh] + dt_bias[myh];
            float sp = (z > 20.0f) ? z : log1pf(expf(z));
            int e = (tok0 + tt) * 8 + lane;
            g_rw[e] = rw;
            g_dsel[e] = -expf(A_log[myh]) * sp;
            int pos = atomicAdd(&g_cursor[myh], 1);
            g_list[myh * LSTRIDE + pos] = e;
        }
    }
}

// ---------------- kernel: grouped q/k/v GEMM (fp16 2-pass, BM=128, 3-stage ring) ----------------
#define ST_SZ 20480
#define WH_OFF 8192
#define WL_OFF 14336
__global__ void __launch_bounds__(256, 2) gemm_qkv_f16(const float* dummy) {
    extern __shared__ __align__(16) unsigned char sdyn[];   // 3 * ST_SZ
    __shared__ int s_ent[128];
    float* Cs = (float*)sdyn;

    int tid = threadIdx.x;
    int h = blockIdx.y;
    int cnt = g_cursor[h];
    int t0 = blockIdx.x * 128;
    if (t0 >= cnt) return;
    if (tid < 128) s_ent[tid] = (t0 + tid < cnt) ? g_list[h * LSTRIDE + t0 + tid] : -1;
    __syncthreads();

    uint32_t sb = (uint32_t)__cvta_generic_to_shared(sdyn);
    int w = tid >> 5, lane = tid & 31;
    int mw = w >> 1, nw = w & 1;
    int g = lane >> 2, tig = lane & 3;

    float acc[2][6][4];
#pragma unroll
    for (int mi = 0; mi < 2; mi++)
#pragma unroll
        for (int i = 0; i < 6; i++)
#pragma unroll
            for (int j = 0; j < 4; j++) acc[mi][i][j] = 0.0f;

    // ldmatrix per-lane byte offsets (within a stage)
    int arow = mw * 32 + (lane & 15);
    int acb  = (lane >> 4) & 1;
    int as_  = (arow >> 1) & 3;
    uint32_t offA0 = (uint32_t)(arow * 64 + ((acb ^ as_) << 4));
    uint32_t offA1 = (uint32_t)(arow * 64 + (((2 | acb) ^ as_) << 4));
    int bcol = nw * 48 + (lane & 7) + ((lane >> 4) << 3);
    int bcb  = (lane >> 3) & 1;
    int bs_  = (bcol >> 1) & 3;
    uint32_t offB0 = (uint32_t)(bcol * 64 + ((bcb ^ bs_) << 4));
    uint32_t offB1 = (uint32_t)(bcol * 64 + (((2 | bcb) ^ bs_) << 4));

    int xu0 = tid, xu1 = tid + 256;
    size_t whbase = (size_t)h * 96 * 512;

#define PRODUCE(stg, kt) do {                                                     \
        uint32_t stoff = sb + (stg) * ST_SZ;                                      \
        int kw0 = (kt) * 16;                                                      \
        { int u = xu0; int row = u >> 2, seg = u & 3;                             \
          int e = s_ent[row];                                                     \
          const void* src = (e >= 0) ? (const void*)&g_xh[(size_t)(e >> 3) * 512 + kw0 + seg * 4] \
                                     : (const void*)g_zero4;                      \
          CP_ASYNC16(stoff + row * 64 + (((seg ^ ((row >> 1) & 3))) << 4), src); } \
        { int u = xu1; int row = u >> 2, seg = u & 3;                             \
          int e = s_ent[row];                                                     \
          const void* src = (e >= 0) ? (const void*)&g_xh[(size_t)(e >> 3) * 512 + kw0 + seg * 4] \
                                     : (const void*)g_zero4;                      \
          CP_ASYNC16(stoff + row * 64 + (((seg ^ ((row >> 1) & 3))) << 4), src); } \
        _Pragma("unroll")                                                         \
        for (int i = 0; i < 3; i++) {                                             \
            int u = tid + i * 256;                                                \
            int hl = (u >= 384);                                                  \
            int v = hl ? (u - 384) : u;                                           \
            int row = v >> 2, seg = v & 3;                                        \
            const unsigned* gsrc = hl ? g_wl : g_wh;                              \
            const void* src = (const void*)&gsrc[whbase + (size_t)row * 512 + kw0 + seg * 4]; \
            uint32_t doff = stoff + (hl ? WL_OFF : WH_OFF) + row * 64             \
                            + (((seg ^ ((row >> 1) & 3))) << 4);                  \
            CP_ASYNC16(doff, src);                                                \
        }                                                                         \
    } while (0)

    PRODUCE(0, 0);
    CP_COMMIT();
    PRODUCE(1, 1);
    CP_COMMIT();

    int stg = 0;
#pragma unroll 1
    for (int kt = 0; kt < 32; kt++) {
        CP_WAIT1();
        __syncthreads();

        uint32_t stX  = sb + stg * ST_SZ;
        uint32_t stWH = stX + WH_OFF;
        uint32_t stWL = stX + WL_OFF;
#pragma unroll
        for (int ka = 0; ka < 2; ka++) {
            uint32_t aoff = (ka == 0) ? offA0 : offA1;
            uint32_t boff = (ka == 0) ? offB0 : offB1;
            unsigned ahi0[4], ahi1[4];
            ldsm_x4(ahi0, stX + aoff);           // mi = 0
            ldsm_x4(ahi1, stX + aoff + 1024);    // mi = 1
#pragma unroll
            for (int p = 0; p < 3; p++) {
                unsigned bh[4], bl[4];
                ldsm_x4(bh, stWH + boff + p * 1024);
                ldsm_x4(bl, stWL + boff + p * 1024);
                mma_f16(acc[0][2 * p],     ahi0, bh);
                mma_f16(acc[0][2 * p],     ahi0, bl);
                mma_f16(acc[1][2 * p],     ahi1, bh);
                mma_f16(acc[1][2 * p],     ahi1, bl);
                mma_f16(acc[0][2 * p + 1], ahi0, bh + 2);
                mma_f16(acc[0][2 * p + 1], ahi0, bl + 2);
                mma_f16(acc[1][2 * p + 1], ahi1, bh + 2);
                mma_f16(acc[1][2 * p + 1], ahi1, bl + 2);
            }
        }
        // produce stage consumed at kt-1 (all warps past this iter's barrier)
        if (kt + 2 < 32) {
            int pst = stg + 2; if (pst >= 3) pst -= 3;
            PRODUCE(pst, kt + 2);
        }
        CP_COMMIT();
        stg = (stg + 1 == 3) ? 0 : stg + 1;
    }
    __syncthreads();   // all consumption done before Cs overlay

#pragma unroll 1
    for (int half = 0; half < 2; half++) {
        if ((mw >> 1) == half) {
#pragma unroll
            for (int mi = 0; mi < 2; mi++)
#pragma unroll
                for (int na = 0; na < 6; na++) {
                    int col = nw * 48 + na * 8 + tig * 2;
                    int row = mw * 32 + mi * 16 + g - half * 64;
                    Cs[row * 97 + col]           = acc[mi][na][0];
                    Cs[row * 97 + col + 1]       = acc[mi][na][1];
                    Cs[(row + 8) * 97 + col]     = acc[mi][na][2];
                    Cs[(row + 8) * 97 + col + 1] = acc[mi][na][3];
                }
        }
        __syncthreads();
#pragma unroll 1
        for (int rep = 0; rep < 8; rep++) {
            int r = rep * 8 + w;
            int e = s_ent[half * 64 + r];
            if (e < 0) continue;
            float wr = g_rw[e];
            float qv = Cs[r * 97 + lane];
            float qs = silu_f(qv);
            float ssq = qs * qs;
#pragma unroll
            for (int o = 16; o > 0; o >>= 1) ssq += __shfl_xor_sync(0xffffffffu, ssq, o);
            g_qsel[(size_t)e * 32 + lane] = qs * rsqrtf(ssq + 1e-6f) * wr;
            float kv = Cs[r * 97 + 32 + lane];
            float ks = silu_f(kv);
            float ssk = ks * ks;
#pragma unroll
            for (int o = 16; o > 0; o >>= 1) ssk += __shfl_xor_sync(0xffffffffu, ssk, o);
            g_ksel[(size_t)e * 32 + lane] = ks * rsqrtf(ssk + 1e-6f);
            float vv = Cs[r * 97 + 64 + lane];
            g_vsel[(size_t)e * 32 + lane] = silu_f(vv);
        }
        __syncthreads();
    }
#undef PRODUCE
}

// ---------------- kernel: chunked scan phase 1 (intra-chunk, vectorized) ----------------
__global__ void chunk_intra() {
    __shared__ float qs[64][36], vs[64][36];
    __shared__ float ksT[32][68];
    __shared__ float As[64][65];
    __shared__ float Ls[64], rr[64];
    int tid = threadIdx.x;
    int cid = blockIdx.x;
    int b = cid >> 8, kk = (cid >> 5) & 7, c = cid & 31;
    size_t e0 = ((size_t)(b * TT + c * CC)) * KK + kk;

#pragma unroll
    for (int it = 0; it < 2; it++) {
        int i = (tid >> 3) + it * 32;
        int c4 = (tid & 7) * 4;
        size_t gidx = (e0 + (size_t)i * KK) * 32 + c4;
        float4 qv = *(const float4*)&g_qsel[gidx];
        float4 kv = *(const float4*)&g_ksel[gidx];
        float4 vv = *(const float4*)&g_vsel[gidx];
        qs[i][c4] = qv.x; qs[i][c4+1] = qv.y; qs[i][c4+2] = qv.z; qs[i][c4+3] = qv.w;
        vs[i][c4] = vv.x; vs[i][c4+1] = vv.y; vs[i][c4+2] = vv.z; vs[i][c4+3] = vv.w;
        ksT[c4+0][i] = kv.x; ksT[c4+1][i] = kv.y; ksT[c4+2][i] = kv.z; ksT[c4+3][i] = kv.w;
    }
    if (tid < 64) Ls[tid] = g_dsel[e0 + (size_t)tid * KK];
    __syncthreads();
    if (tid == 0) {
        float a = 0.0f;
        for (int i = 0; i < 64; i++) { a += Ls[i]; Ls[i] = a; }
    }
    __syncthreads();
    if (tid < 64) rr[tid] = __expf(Ls[63] - Ls[tid]);

    {
        int i = tid >> 2, s0 = (tid & 3) * 16;
        float acc[16];
#pragma unroll
        for (int j = 0; j < 16; j++) acc[j] = 0.0f;
#pragma unroll 4
        for (int n = 0; n < 32; n++) {
            float qv = qs[i][n];
            float4 k0_ = *(const float4*)&ksT[n][s0];
            float4 k1_ = *(const float4*)&ksT[n][s0 + 4];
            float4 k2_ = *(const float4*)&ksT[n][s0 + 8];
            float4 k3_ = *(const float4*)&ksT[n][s0 + 12];
            acc[0]  = fmaf(qv, k0_.x, acc[0]);  acc[1]  = fmaf(qv, k0_.y, acc[1]);
            acc[2]  = fmaf(qv, k0_.z, acc[2]);  acc[3]  = fmaf(qv, k0_.w, acc[3]);
            acc[4]  = fmaf(qv, k1_.x, acc[4]);  acc[5]  = fmaf(qv, k1_.y, acc[5]);
            acc[6]  = fmaf(qv, k1_.z, acc[6]);  acc[7]  = fmaf(qv, k1_.w, acc[7]);
            acc[8]  = fmaf(qv, k2_.x, acc[8]);  acc[9]  = fmaf(qv, k2_.y, acc[9]);
            acc[10] = fmaf(qv, k2_.z, acc[10]); acc[11] = fmaf(qv, k2_.w, acc[11]);
            acc[12] = fmaf(qv, k3_.x, acc[12]); acc[13] = fmaf(qv, k3_.y, acc[13]);
            acc[14] = fmaf(qv, k3_.z, acc[14]); acc[15] = fmaf(qv, k3_.w, acc[15]);
        }
        float Li = Ls[i];
#pragma unroll
        for (int j = 0; j < 16; j++) {
            int s = s0 + j;
            As[i][s] = (s <= i) ? acc[j] * __expf(Li - Ls[s]) : 0.0f;
        }
        int cg = (tid & 3) * 8;
        float ei = __expf(Li);
        size_t gq = (e0 + (size_t)i * KK) * 32 + cg;
#pragma unroll
        for (int j = 0; j < 8; j++)
            g_qsel[gq + j] = qs[i][cg + j] * ei;
    }
    __syncthreads();

    {
        int i = tid >> 2, vg = (tid & 3) * 8;
        float y[8];
#pragma unroll
        for (int j = 0; j < 8; j++) y[j] = 0.0f;
#pragma unroll 4
        for (int s = 0; s < 64; s++) {
            float a = As[i][s];
            float4 v0 = *(const float4*)&vs[s][vg];
            float4 v1 = *(const float4*)&vs[s][vg + 4];
            y[0] = fmaf(a, v0.x, y[0]); y[1] = fmaf(a, v0.y, y[1]);
            y[2] = fmaf(a, v0.z, y[2]); y[3] = fmaf(a, v0.w, y[3]);
            y[4] = fmaf(a, v1.x, y[4]); y[5] = fmaf(a, v1.y, y[5]);
            y[6] = fmaf(a, v1.z, y[6]); y[7] = fmaf(a, v1.w, y[7]);
        }
        size_t gy = (e0 + (size_t)i * KK) * 32 + vg;
        *(float4*)&g_yslot[gy]     = make_float4(y[0], y[1], y[2], y[3]);
        *(float4*)&g_yslot[gy + 4] = make_float4(y[4], y[5], y[6], y[7]);
    }

    {
        int n = tid >> 3, vg = (tid & 7) * 4;
        float u[4] = {0.f, 0.f, 0.f, 0.f};
#pragma unroll 4
        for (int s = 0; s < 64; s++) {
            float kd = ksT[n][s] * rr[s];
            float4 vv = *(const float4*)&vs[s][vg];
            u[0] = fmaf(kd, vv.x, u[0]); u[1] = fmaf(kd, vv.y, u[1]);
            u[2] = fmaf(kd, vv.z, u[2]); u[3] = fmaf(kd, vv.w, u[3]);
        }
        *(float4*)&g_U[(size_t)cid * 1024 + n * 32 + vg] = make_float4(u[0], u[1], u[2], u[3]);
    }
    if (tid == 0) g_P63[cid] = __expf(Ls[63]);
}

// ---------------- kernel: chunked scan phase 2 (state propagation) ----------------
__global__ void chunk_state(const float* __restrict__ S0,
                            float* __restrict__ sfin) {
    int tid = threadIdx.x;
    int seq = blockIdx.x;
    float S = S0[(size_t)seq * 1024 + tid];
#pragma unroll 1
    for (int c = 0; c < NCH; c++) {
        int cid = seq * NCH + c;
        g_Schunk[(size_t)cid * 1024 + tid] = S;
        float P = g_P63[cid];
        S = fmaf(P, S, g_U[(size_t)cid * 1024 + tid]);
    }
    if (sfin) sfin[(size_t)seq * 1024 + tid] = S;
}

// ---------------- kernel: chunked scan phase 3 (cross-chunk term) ----------------
__global__ void chunk_cross() {
    __shared__ float Sc[1024];
    __shared__ float qds[64][33];
    int tid = threadIdx.x;
    int cid = blockIdx.x;
    int b = cid >> 8, kk = (cid >> 5) & 7, c = cid & 31;
    size_t e0 = ((size_t)(b * TT + c * CC)) * KK + kk;

    {
        float4 s4 = *(const float4*)&g_Schunk[(size_t)cid * 1024 + tid * 4];
        *(float4*)&Sc[tid * 4] = s4;
    }
#pragma unroll
    for (int it = 0; it < 2; it++) {
        int i = (tid >> 3) + it * 32;
        int c4 = (tid & 7) * 4;
        float4 qv = *(const float4*)&g_qsel[(e0 + (size_t)i * KK) * 32 + c4];
        qds[i][c4] = qv.x; qds[i][c4+1] = qv.y; qds[i][c4+2] = qv.z; qds[i][c4+3] = qv.w;
    }
    __syncthreads();

    int i = tid >> 2, vg = (tid & 3) * 8;
    size_t gy = (e0 + (size_t)i * KK) * 32 + vg;
    float4 y0 = *(const float4*)&g_yslot[gy];
    float4 y1 = *(const float4*)&g_yslot[gy + 4];
    float y[8] = {y0.x, y0.y, y0.z, y0.w, y1.x, y1.y, y1.z, y1.w};
#pragma unroll 8
    for (int n = 0; n < 32; n++) {
        float qv = qds[i][n];
#pragma unroll
        for (int j = 0; j < 8; j++)
            y[j] = fmaf(qv, Sc[n * 32 + vg + j], y[j]);
    }
    *(float4*)&g_yslot[gy]     = make_float4(y[0], y[1], y[2], y[3]);
    *(float4*)&g_yslot[gy + 4] = make_float4(y[4], y[5], y[6], y[7]);
}

// ---------------- kernel: slot reduce -> g_ysum ----------------
__global__ void ysum_kernel() {
    int u = blockIdx.x * 256 + threadIdx.x;
    int t = u >> 5, v = u & 31;
    float s = 0.0f;
    size_t p = (size_t)t * KK * 32 + v;
#pragma unroll
    for (int kk = 0; kk < KK; kk++) s += g_yslot[p + kk * 32];
    g_ysum[u] = s;
}

// ---------------- kernel: output projection ----------------
__global__ void outproj_kernel(float* __restrict__ out) {
    __shared__ float ysum[32][32];
    int tid = threadIdx.x;
    int tok0 = blockIdx.x * 32;
    int d = blockIdx.y * 256 + tid;

#pragma unroll
    for (int u = tid; u < 1024; u += 256) {
        int tk = u >> 5, v = u & 31;
        ysum[tk][v] = g_ysum[(size_t)(tok0) * 32 + u];
    }
    __syncthreads();

    float wreg[32];
#pragma unroll
    for (int vv = 0; vv < 32; vv++) wreg[vv] = g_WoT[vv * DD + d];

#pragma unroll 4
    for (int tk = 0; tk < 32; tk++) {
        float acc = 0.0f;
#pragma unroll
        for (int vv = 0; vv < 32; vv += 4) {
            float4 y4 = *(const float4*)&ysum[tk][vv];
            acc = fmaf(wreg[vv],     y4.x, acc);
            acc = fmaf(wreg[vv + 1], y4.y, acc);
            acc = fmaf(wreg[vv + 2], y4.z, acc);
            acc = fmaf(wreg[vv + 3], y4.w, acc);
        }
        out[(size_t)(tok0 + tk) * DD + d] = acc;
    }
}

// ---------------- launch ----------------
extern "C" void kernel_launch(void* const* d_in, const int* in_sizes, int n_in,
                              void* d_out, int out_size) {
    const float* x       = (const float*)d_in[0];
    const float* Wr      = (const float*)d_in[1];
    const float* Wq      = (const float*)d_in[2];
    const float* Wk      = (const float*)d_in[3];
    const float* Wv      = (const float*)d_in[4];
    const float* Wa      = (const float*)d_in[5];
    const float* A_log   = (const float*)d_in[6];
    const float* dt_bias = (const float*)d_in[7];
    const float* Wo      = (const float*)d_in[8];
    const float* S0      = (const float*)d_in[9];
    float* out = (float*)d_out;

    const long y_elems = (long)NT * DD;
    const long s_elems = (long)BB * KK * NSd * HVd;
    float* sfin = ((long)out_size >= y_elems + s_elems) ? (out + y_elems) : nullptr;

    cudaFuncSetAttribute(gemm_qkv_f16,
                         cudaFuncAttributeMaxDynamicSharedMemorySize, 3 * ST_SZ);

    prep_kernel<<<7360, 256>>>(Wo, x, Wq, Wk, Wv, Wr, Wa);
    gemm_ra_f16<<<NT / 64, 256>>>(nullptr);
    route_kernel<<<NT / 16, 256>>>(A_log, dt_bias);
    gemm_qkv_f16<<<dim3(QTILES, HH), 256, 3 * ST_SZ>>>(nullptr);
    chunk_intra<<<NCHUNKS, 256>>>();
    chunk_state<<<BB * KK, 1024>>>(S0, sfin);
    chunk_cross<<<NCHUNKS, 256>>>();
    ysum_kernel<<<NT * 32 / 256, 256>>>();
    outproj_kernel<<<dim3(NT / 32, 4), 256>>>(out);
}

// round 16
// speedup vs baseline: 1.0158x; 1.0096x over previous
#include <cuda_runtime.h>
#include <cuda_fp16.h>
#include <stdint.h>
#include <math.h>

// Problem constants
#define BB   4
#define TT   2048
#define DD   1024
#define HH   64
#define NSd  32
#define KK   8
#define HVd  32
#define NT   8192      // BB*TT tokens
#define NTS  65536     // NT*KK token-slots
#define QTILES 16      // 128-token tiles per head
#define LSTRIDE 2048   // per-head list stride
#define CC   64        // chunk length
#define NCH  32        // chunks per sequence
#define NCHUNKS 1024   // BB*KK*NCH

// ---------------- scratch (static device memory; no allocation) ----------------
__device__ float g_ra[NT * 128];
__device__ float g_rw[NTS];
__device__ float g_dsel[NTS];             // per-slot decay EXPONENT (<=0)
__device__ int   g_cursor[HH];
__device__ int   g_list[HH * LSTRIDE];
__device__ float g_qsel[NTS * 32];        // phase1 overwrites with qd = q*exp(L)
__device__ float g_ksel[NTS * 32];
__device__ float g_vsel[NTS * 32];
__device__ float g_yslot[NTS * 32];
__device__ float g_ysum[NT * 32];
__device__ float g_WoT[32 * DD];
__device__ float g_U[NCHUNKS * 1024];
__device__ float g_P63[NCHUNKS];
__device__ float g_Schunk[NCHUNKS * 1024];
// pre-converted fp16 operands (packed half2 words)
__device__ unsigned g_xh[NT * 512];           // x hi
__device__ unsigned g_xl[NT * 512];           // x lo (for gemm_ra 3-pass)
__device__ unsigned g_wh[HH * 96 * 512];      // W qkv hi
__device__ unsigned g_wl[HH * 96 * 512];      // W qkv lo  (unused by qkv now; kept for layout stability)
__device__ unsigned g_wrah[128 * 512];        // [Wr;Wa] hi
__device__ unsigned g_wral[128 * 512];        // [Wr;Wa] lo
__device__ float g_zero4[4] = {0.f, 0.f, 0.f, 0.f};

// ---------------- helpers ----------------
__device__ __forceinline__ float silu_f(float x) {
    return x / (1.0f + expf(-x));
}

__device__ __forceinline__ void f16_split2(float x0, float x1, unsigned& hi, unsigned& lo) {
    __half2 h2 = __floats2half2_rn(x0, x1);
    float h0 = __low2float(h2);
    float h1 = __high2float(h2);
    __half2 l2 = __floats2half2_rn(x0 - h0, x1 - h1);
    hi = *(unsigned*)&h2;
    lo = *(unsigned*)&l2;
}

__device__ __forceinline__ void mma_f16(float* c, const unsigned* a, const unsigned* b) {
    asm volatile(
        "mma.sync.aligned.m16n8k16.row.col.f32.f16.f16.f32 "
        "{%0,%1,%2,%3}, {%4,%5,%6,%7}, {%8,%9}, {%0,%1,%2,%3};"
        : "+f"(c[0]), "+f"(c[1]), "+f"(c[2]), "+f"(c[3])
        : "r"(a[0]), "r"(a[1]), "r"(a[2]), "r"(a[3]), "r"(b[0]), "r"(b[1]));
}

__device__ __forceinline__ void ldsm_x4(unsigned* r, uint32_t addr) {
    asm volatile("ldmatrix.sync.aligned.m8n8.x4.shared.b16 {%0,%1,%2,%3}, [%4];"
        : "=r"(r[0]), "=r"(r[1]), "=r"(r[2]), "=r"(r[3]) : "r"(addr));
}

#define CP_ASYNC16(dst, src) \
    asm volatile("cp.async.cg.shared.global [%0], [%1], 16;" :: "r"(dst), "l"(src) : "memory")
#define CP_COMMIT() asm volatile("cp.async.commit_group;" ::: "memory")
#define CP_WAIT1()  asm volatile("cp.async.wait_group 1;" ::: "memory")

// swizzled word index within a 16-word (64B) smem row
__device__ __forceinline__ int swz_word(int row, int kw) {
    return row * 16 + ((((kw >> 2) ^ ((row >> 1) & 3))) << 2) + (kw & 3);
}

__device__ __forceinline__ void split8_store(const float4 p0, const float4 p1,
                                             unsigned* dh, unsigned* dl) {
    uint4 oh, ol;
    unsigned hh_, ll_;
    f16_split2(p0.x, p0.y, hh_, ll_); oh.x = hh_; ol.x = ll_;
    f16_split2(p0.z, p0.w, hh_, ll_); oh.y = hh_; ol.y = ll_;
    f16_split2(p1.x, p1.y, hh_, ll_); oh.z = hh_; ol.z = ll_;
    f16_split2(p1.z, p1.w, hh_, ll_); oh.w = hh_; ol.w = ll_;
    *(uint4*)dh = oh;
    *(uint4*)dl = ol;
}

// ---------------- kernel: fused prep (WoT transpose, cursors, all fp16 conversions) ----------------
__global__ void prep_kernel(const float* __restrict__ Wo,
                            const float* __restrict__ x,
                            const float* __restrict__ Wq,
                            const float* __restrict__ Wk,
                            const float* __restrict__ Wv,
                            const float* __restrict__ Wr,
                            const float* __restrict__ Wa) {
    int blk = blockIdx.x;
    int tid = threadIdx.x;
    if (blk < 128) {
        int o = blk * 256 + tid;
        int v = o >> 10, d = o & 1023;
        g_WoT[o] = Wo[d * 32 + v];
        if (o < HH) g_cursor[o] = 0;
    } else if (blk < 4224) {
        int u = (blk - 128) * 256 + tid;            // (token, wordgrp)
        int tok = u >> 7, w4 = u & 127;
        const float* src = x + (size_t)tok * DD + w4 * 8;
        size_t base = (size_t)tok * 512 + w4 * 4;
        split8_store(*(const float4*)src, *(const float4*)(src + 4),
                     &g_xh[base], &g_xl[base]);
    } else if (blk < 7296) {
        int u = (blk - 4224) * 256 + tid;           // (h, row 0..95, wordgrp)
        int h = u / (96 * 128);
        int rem = u - h * 96 * 128;
        int r = rem >> 7, w4 = rem & 127;
        const float* src = (r < 32) ? (Wq + (size_t)(h * 32 + r) * DD)
                         : (r < 64) ? (Wk + (size_t)(h * 32 + r - 32) * DD)
                                    : (Wv + (size_t)(h * 32 + r - 64) * DD);
        src += w4 * 8;
        size_t base = ((size_t)h * 96 + r) * 512 + w4 * 4;
        split8_store(*(const float4*)src, *(const float4*)(src + 4),
                     &g_wh[base], &g_wl[base]);
    } else {
        int u = (blk - 7296) * 256 + tid;           // (row 0..127, wordgrp)
        int r = u >> 7, w4 = u & 127;
        const float* src = (r < 64) ? (Wr + (size_t)r * DD) : (Wa + (size_t)(r - 64) * DD);
        src += w4 * 8;
        size_t base = (size_t)r * 512 + w4 * 4;
        split8_store(*(const float4*)src, *(const float4*)(src + 4),
                     &g_wrah[base], &g_wral[base]);
    }
}

// ---------------- kernel: router + decay GEMM (fp16 3-pass, cp.async, BM=64) ----------------
#define RA_ST   24576
#define RA_XL   4096
#define RA_WH   8192
#define RA_WL   16384
__global__ void __launch_bounds__(256) gemm_ra_f16(const float* dummy) {
    __shared__ __align__(16) unsigned char sbuf[2 * RA_ST];
    int tid = threadIdx.x;
    int m0 = blockIdx.x * 64;
    uint32_t sb = (uint32_t)__cvta_generic_to_shared(sbuf);
    int w = tid >> 5, lane = tid & 31;
    int mw = w >> 2, nw = w & 3;
    int g = lane >> 2, tig = lane & 3;

    float acc[2][4][4];
#pragma unroll
    for (int mi = 0; mi < 2; mi++)
#pragma unroll
        for (int i = 0; i < 4; i++)
#pragma unroll
            for (int j = 0; j < 4; j++) acc[mi][i][j] = 0.0f;

#define RA_PRODUCE(stg, kt) do {                                                   \
        uint32_t stoff = sb + (stg) * RA_ST;                                       \
        int kw0 = (kt) * 16;                                                       \
        _Pragma("unroll")                                                          \
        for (int i = 0; i < 6; i++) {                                              \
            int u = tid + i * 256;                                                 \
            if (u < 256) {            /* X hi */                                   \
                int row = u >> 2, seg = u & 3;                                     \
                const void* src = (const void*)&g_xh[(size_t)(m0 + row) * 512 + kw0 + seg * 4]; \
                CP_ASYNC16(stoff + row * 64 + (((seg ^ ((row >> 1) & 3))) << 4), src); \
            } else if (u < 512) {     /* X lo */                                   \
                int v = u - 256; int row = v >> 2, seg = v & 3;                    \
                const void* src = (const void*)&g_xl[(size_t)(m0 + row) * 512 + kw0 + seg * 4]; \
                CP_ASYNC16(stoff + RA_XL + row * 64 + (((seg ^ ((row >> 1) & 3))) << 4), src); \
            } else if (u < 1024) {    /* W hi */                                   \
                int v = u - 512; int row = v >> 2, seg = v & 3;                    \
                const void* src = (const void*)&g_wrah[(size_t)row * 512 + kw0 + seg * 4]; \
                CP_ASYNC16(stoff + RA_WH + row * 64 + (((seg ^ ((row >> 1) & 3))) << 4), src); \
            } else {                  /* W lo */                                   \
                int v = u - 1024; int row = v >> 2, seg = v & 3;                   \
                const void* src = (const void*)&g_wral[(size_t)row * 512 + kw0 + seg * 4]; \
                CP_ASYNC16(stoff + RA_WL + row * 64 + (((seg ^ ((row >> 1) & 3))) << 4), src); \
            }                                                                      \
        }                                                                          \
    } while (0)

    RA_PRODUCE(0, 0);
    CP_COMMIT();

#pragma unroll 1
    for (int kt = 0; kt < 32; kt++) {
        int cur = kt & 1, nxt = cur ^ 1;
        if (kt + 1 < 32) RA_PRODUCE(nxt, kt + 1);
        CP_COMMIT();
        CP_WAIT1();
        __syncthreads();

        const unsigned* XH = (const unsigned*)(sbuf + cur * RA_ST);
        const unsigned* XL = (const unsigned*)(sbuf + cur * RA_ST + RA_XL);
        const unsigned* WH = (const unsigned*)(sbuf + cur * RA_ST + RA_WH);
        const unsigned* WL = (const unsigned*)(sbuf + cur * RA_ST + RA_WL);
#pragma unroll
        for (int ka = 0; ka < 2; ka++) {
            int kw = ka * 8 + tig;
            unsigned ahi[2][4], alo[2][4];
#pragma unroll
            for (int mi = 0; mi < 2; mi++) {
                int r0 = mw * 32 + mi * 16 + g;
                ahi[mi][0] = XH[swz_word(r0, kw)];
                ahi[mi][1] = XH[swz_word(r0 + 8, kw)];
                ahi[mi][2] = XH[swz_word(r0, kw + 4)];
                ahi[mi][3] = XH[swz_word(r0 + 8, kw + 4)];
                alo[mi][0] = XL[swz_word(r0, kw)];
                alo[mi][1] = XL[swz_word(r0 + 8, kw)];
                alo[mi][2] = XL[swz_word(r0, kw + 4)];
                alo[mi][3] = XL[swz_word(r0 + 8, kw + 4)];
            }
#pragma unroll
            for (int na = 0; na < 4; na++) {
                int col = nw * 32 + na * 8 + g;
                unsigned bhi[2], blo[2];
                bhi[0] = WH[swz_word(col, kw)];
                bhi[1] = WH[swz_word(col, kw + 4)];
                blo[0] = WL[swz_word(col, kw)];
                blo[1] = WL[swz_word(col, kw + 4)];
#pragma unroll
                for (int mi = 0; mi < 2; mi++) {
                    mma_f16(acc[mi][na], ahi[mi], bhi);
                    mma_f16(acc[mi][na], ahi[mi], blo);
                    mma_f16(acc[mi][na], alo[mi], bhi);
                }
            }
        }
        __syncthreads();
    }
#pragma unroll
    for (int mi = 0; mi < 2; mi++)
#pragma unroll
        for (int na = 0; na < 4; na++) {
            int col = nw * 32 + na * 8 + tig * 2;
            int row = m0 + mw * 32 + mi * 16 + g;
            *(float2*)&g_ra[(size_t)row * 128 + col]       = make_float2(acc[mi][na][0], acc[mi][na][1]);
            *(float2*)&g_ra[(size_t)(row + 8) * 128 + col] = make_float2(acc[mi][na][2], acc[mi][na][3]);
        }
#undef RA_PRODUCE
}

// ---------------- kernel: routing (top-8, rw, decay, direct list append) ----------------
__global__ void route_kernel(const float* __restrict__ A_log,
                             const float* __restrict__ dt_bias) {
    int lane = threadIdx.x & 31;
    int w = threadIdx.x >> 5;
    int tok0 = blockIdx.x * 16 + w * 2;

    float v0[2], v1[2];
    const float* ra0 = g_ra + (size_t)tok0 * 128;
    const float* ra1 = ra0 + 128;
    v0[0] = ra0[lane]; v1[0] = ra0[lane + 32];
    v0[1] = ra1[lane]; v1[1] = ra1[lane + 32];
    int i0 = lane, i1 = lane + 32;
    float topv[2][8]; int tophi[2][8];
#pragma unroll
    for (int it = 0; it < 8; it++) {
#pragma unroll
        for (int tt = 0; tt < 2; tt++) {
            float bv; int bi;
            if (v0[tt] > v1[tt] || (v0[tt] == v1[tt] && i0 < i1)) { bv = v0[tt]; bi = i0; }
            else                                                   { bv = v1[tt]; bi = i1; }
#pragma unroll
            for (int off = 16; off > 0; off >>= 1) {
                float ov = __shfl_xor_sync(0xffffffffu, bv, off);
                int   oi = __shfl_xor_sync(0xffffffffu, bi, off);
                if (ov > bv || (ov == bv && oi < bi)) { bv = ov; bi = oi; }
            }
            topv[tt][it] = bv; tophi[tt][it] = bi;
            if (bi == i0) v0[tt] = -INFINITY;
            if (bi == i1) v1[tt] = -INFINITY;
        }
    }
#pragma unroll
    for (int tt = 0; tt < 2; tt++) {
        float s = 0.0f;
#pragma unroll
        for (int j = 0; j < 8; j++) s += expf(topv[tt][j] - topv[tt][0]);

        float myv = 0.0f; int myh = 0;
#pragma unroll
        for (int it = 0; it < 8; it++)
            if (lane == it) { myv = topv[tt][it]; myh = tophi[tt][it]; }

        if (lane < 8) {
            const float* ra = (tt == 0) ? ra0 : ra1;
            float rw = expf(myv - topv[tt][0]) / s;
            float z = ra[64 + myh] + dt_bias[myh];
            float sp = (z > 20.0f) ? z : log1pf(expf(z));
            int e = (tok0 + tt) * 8 + lane;
            g_rw[e] = rw;
            g_dsel[e] = -expf(A_log[myh]) * sp;
            int pos = atomicAdd(&g_cursor[myh], 1);
            g_list[myh * LSTRIDE + pos] = e;
        }
    }
}

// ---------------- kernel: grouped q/k/v GEMM (fp16 single-pass, BM=128, 3-stage ring) ----------------
#define ST_SZ 14336
#define WH_OFF 8192
__global__ void __launch_bounds__(256, 2) gemm_qkv_f16(const float* dummy) {
    __shared__ __align__(16) unsigned char sbuf[3 * ST_SZ];   // 43008 B
    __shared__ int s_ent[128];
    float* Cs = (float*)sbuf;

    int tid = threadIdx.x;
    int h = blockIdx.y;
    int cnt = g_cursor[h];
    int t0 = blockIdx.x * 128;
    if (t0 >= cnt) return;
    if (tid < 128) s_ent[tid] = (t0 + tid < cnt) ? g_list[h * LSTRIDE + t0 + tid] : -1;
    __syncthreads();

    uint32_t sb = (uint32_t)__cvta_generic_to_shared(sbuf);
    int w = tid >> 5, lane = tid & 31;
    int mw = w >> 1, nw = w & 1;
    int g = lane >> 2, tig = lane & 3;

    float acc[2][6][4];
#pragma unroll
    for (int mi = 0; mi < 2; mi++)
#pragma unroll
        for (int i = 0; i < 6; i++)
#pragma unroll
            for (int j = 0; j < 4; j++) acc[mi][i][j] = 0.0f;

    // ldmatrix per-lane byte offsets (within a stage)
    int arow = mw * 32 + (lane & 15);
    int acb  = (lane >> 4) & 1;
    int as_  = (arow >> 1) & 3;
    uint32_t offA0 = (uint32_t)(arow * 64 + ((acb ^ as_) << 4));
    uint32_t offA1 = (uint32_t)(arow * 64 + (((2 | acb) ^ as_) << 4));
    int bcol = nw * 48 + (lane & 7) + ((lane >> 4) << 3);
    int bcb  = (lane >> 3) & 1;
    int bs_  = (bcol >> 1) & 3;
    uint32_t offB0 = (uint32_t)(bcol * 64 + ((bcb ^ bs_) << 4));
    uint32_t offB1 = (uint32_t)(bcol * 64 + (((2 | bcb) ^ bs_) << 4));

    int xu0 = tid, xu1 = tid + 256;
    size_t whbase = (size_t)h * 96 * 512;

#define PRODUCE(stg, kt) do {                                                     \
        uint32_t stoff = sb + (stg) * ST_SZ;                                      \
        int kw0 = (kt) * 16;                                                      \
        { int u = xu0; int row = u >> 2, seg = u & 3;                             \
          int e = s_ent[row];                                                     \
          const void* src = (e >= 0) ? (const void*)&g_xh[(size_t)(e >> 3) * 512 + kw0 + seg * 4] \
                                     : (const void*)g_zero4;                      \
          CP_ASYNC16(stoff + row * 64 + (((seg ^ ((row >> 1) & 3))) << 4), src); } \
        { int u = xu1; int row = u >> 2, seg = u & 3;                             \
          int e = s_ent[row];                                                     \
          const void* src = (e >= 0) ? (const void*)&g_xh[(size_t)(e >> 3) * 512 + kw0 + seg * 4] \
                                     : (const void*)g_zero4;                      \
          CP_ASYNC16(stoff + row * 64 + (((seg ^ ((row >> 1) & 3))) << 4), src); } \
        _Pragma("unroll")                                                         \
        for (int i = 0; i < 2; i++) {                                             \
            int u = tid + i * 256;                                                \
            if (u < 384) {                                                        \
                int row = u >> 2, seg = u & 3;                                    \
                const void* src = (const void*)&g_wh[whbase + (size_t)row * 512 + kw0 + seg * 4]; \
                uint32_t doff = stoff + WH_OFF + row * 64                         \
                                + (((seg ^ ((row >> 1) & 3))) << 4);              \
                CP_ASYNC16(doff, src);                                            \
            }                                                                     \
        }                                                                         \
    } while (0)

    PRODUCE(0, 0);
    CP_COMMIT();
    PRODUCE(1, 1);
    CP_COMMIT();

    int stg = 0;
#pragma unroll 1
    for (int kt = 0; kt < 32; kt++) {
        CP_WAIT1();
        __syncthreads();

        uint32_t stX  = sb + stg * ST_SZ;
        uint32_t stWH = stX + WH_OFF;
#pragma unroll
        for (int ka = 0; ka < 2; ka++) {
            uint32_t aoff = (ka == 0) ? offA0 : offA1;
            uint32_t boff = (ka == 0) ? offB0 : offB1;
            unsigned ahi0[4], ahi1[4];
            ldsm_x4(ahi0, stX + aoff);           // mi = 0
            ldsm_x4(ahi1, stX + aoff + 1024);    // mi = 1
#pragma unroll
            for (int p = 0; p < 3; p++) {
                unsigned bh[4];
                ldsm_x4(bh, stWH + boff + p * 1024);
                mma_f16(acc[0][2 * p],     ahi0, bh);
                mma_f16(acc[1][2 * p],     ahi1, bh);
                mma_f16(acc[0][2 * p + 1], ahi0, bh + 2);
                mma_f16(acc[1][2 * p + 1], ahi1, bh + 2);
            }
        }
        if (kt + 2 < 32) {
            int pst = stg + 2; if (pst >= 3) pst -= 3;
            PRODUCE(pst, kt + 2);
        }
        CP_COMMIT();
        stg = (stg + 1 == 3) ? 0 : stg + 1;
    }
    __syncthreads();   // all consumption done before Cs overlay

#pragma unroll 1
    for (int half = 0; half < 2; half++) {
        if ((mw >> 1) == half) {
#pragma unroll
            for (int mi = 0; mi < 2; mi++)
#pragma unroll
                for (int na = 0; na < 6; na++) {
                    int col = nw * 48 + na * 8 + tig * 2;
                    int row = mw * 32 + mi * 16 + g - half * 64;
                    Cs[row * 97 + col]           = acc[mi][na][0];
                    Cs[row * 97 + col + 1]       = acc[mi][na][1];
                    Cs[(row + 8) * 97 + col]     = acc[mi][na][2];
                    Cs[(row + 8) * 97 + col + 1] = acc[mi][na][3];
                }
        }
        __syncthreads();
#pragma unroll 1
        for (int rep = 0; rep < 8; rep++) {
            int r = rep * 8 + w;
            int e = s_ent[half * 64 + r];
            if (e < 0) continue;
            float wr = g_rw[e];
            float qv = Cs[r * 97 + lane];
            float qs = silu_f(qv);
            float ssq = qs * qs;
#pragma unroll
            for (int o = 16; o > 0; o >>= 1) ssq += __shfl_xor_sync(0xffffffffu, ssq, o);
            g_qsel[(size_t)e * 32 + lane] = qs * rsqrtf(ssq + 1e-6f) * wr;
            float kv = Cs[r * 97 + 32 + lane];
            float ks = silu_f(kv);
            float ssk = ks * ks;
#pragma unroll
            for (int o = 16; o > 0; o >>= 1) ssk += __shfl_xor_sync(0xffffffffu, ssk, o);
            g_ksel[(size_t)e * 32 + lane] = ks * rsqrtf(ssk + 1e-6f);
            float vv = Cs[r * 97 + 64 + lane];
            g_vsel[(size_t)e * 32 + lane] = silu_f(vv);
        }
        __syncthreads();
    }
#undef PRODUCE
}

// ---------------- kernel: chunked scan phase 1 (intra-chunk, vectorized) ----------------
__global__ void chunk_intra() {
    __shared__ float qs[64][36], vs[64][36];
    __shared__ float ksT[32][68];
    __shared__ float As[64][65];
    __shared__ float Ls[64], rr[64];
    int tid = threadIdx.x;
    int cid = blockIdx.x;
    int b = cid >> 8, kk = (cid >> 5) & 7, c = cid & 31;
    size_t e0 = ((size_t)(b * TT + c * CC)) * KK + kk;

#pragma unroll
    for (int it = 0; it < 2; it++) {
        int i = (tid >> 3) + it * 32;
        int c4 = (tid & 7) * 4;
        size_t gidx = (e0 + (size_t)i * KK) * 32 + c4;
        float4 qv = *(const float4*)&g_qsel[gidx];
        float4 kv = *(const float4*)&g_ksel[gidx];
        float4 vv = *(const float4*)&g_vsel[gidx];
        qs[i][c4] = qv.x; qs[i][c4+1] = qv.y; qs[i][c4+2] = qv.z; qs[i][c4+3] = qv.w;
        vs[i][c4] = vv.x; vs[i][c4+1] = vv.y; vs[i][c4+2] = vv.z; vs[i][c4+3] = vv.w;
        ksT[c4+0][i] = kv.x; ksT[c4+1][i] = kv.y; ksT[c4+2][i] = kv.z; ksT[c4+3][i] = kv.w;
    }
    if (tid < 64) Ls[tid] = g_dsel[e0 + (size_t)tid * KK];
    __syncthreads();
    if (tid == 0) {
        float a = 0.0f;
        for (int i = 0; i < 64; i++) { a += Ls[i]; Ls[i] = a; }
    }
    __syncthreads();
    if (tid < 64) rr[tid] = __expf(Ls[63] - Ls[tid]);

    {
        int i = tid >> 2, s0 = (tid & 3) * 16;
        float acc[16];
#pragma unroll
        for (int j = 0; j < 16; j++) acc[j] = 0.0f;
#pragma unroll 4
        for (int n = 0; n < 32; n++) {
            float qv = qs[i][n];
            float4 k0_ = *(const float4*)&ksT[n][s0];
            float4 k1_ = *(const float4*)&ksT[n][s0 + 4];
            float4 k2_ = *(const float4*)&ksT[n][s0 + 8];
            float4 k3_ = *(const float4*)&ksT[n][s0 + 12];
            acc[0]  = fmaf(qv, k0_.x, acc[0]);  acc[1]  = fmaf(qv, k0_.y, acc[1]);
            acc[2]  = fmaf(qv, k0_.z, acc[2]);  acc[3]  = fmaf(qv, k0_.w, acc[3]);
            acc[4]  = fmaf(qv, k1_.x, acc[4]);  acc[5]  = fmaf(qv, k1_.y, acc[5]);
            acc[6]  = fmaf(qv, k1_.z, acc[6]);  acc[7]  = fmaf(qv, k1_.w, acc[7]);
            acc[8]  = fmaf(qv, k2_.x, acc[8]);  acc[9]  = fmaf(qv, k2_.y, acc[9]);
            acc[10] = fmaf(qv, k2_.z, acc[10]); acc[11] = fmaf(qv, k2_.w, acc[11]);
            acc[12] = fmaf(qv, k3_.x, acc[12]); acc[13] = fmaf(qv, k3_.y, acc[13]);
            acc[14] = fmaf(qv, k3_.z, acc[14]); acc[15] = fmaf(qv, k3_.w, acc[15]);
        }
        float Li = Ls[i];
#pragma unroll
        for (int j = 0; j < 16; j++) {
            int s = s0 + j;
            As[i][s] = (s <= i) ? acc[j] * __expf(Li - Ls[s]) : 0.0f;
        }
        int cg = (tid & 3) * 8;
        float ei = __expf(Li);
        size_t gq = (e0 + (size_t)i * KK) * 32 + cg;
#pragma unroll
        for (int j = 0; j < 8; j++)
            g_qsel[gq + j] = qs[i][cg + j] * ei;
    }
    __syncthreads();

    {
        int i = tid >> 2, vg = (tid & 3) * 8;
        float y[8];
#pragma unroll
        for (int j = 0; j < 8; j++) y[j] = 0.0f;
#pragma unroll 4
        for (int s = 0; s < 64; s++) {
            float a = As[i][s];
            float4 v0 = *(const float4*)&vs[s][vg];
            float4 v1 = *(const float4*)&vs[s][vg + 4];
            y[0] = fmaf(a, v0.x, y[0]); y[1] = fmaf(a, v0.y, y[1]);
            y[2] = fmaf(a, v0.z, y[2]); y[3] = fmaf(a, v0.w, y[3]);
            y[4] = fmaf(a, v1.x, y[4]); y[5] = fmaf(a, v1.y, y[5]);
            y[6] = fmaf(a, v1.z, y[6]); y[7] = fmaf(a, v1.w, y[7]);
        }
        size_t gy = (e0 + (size_t)i * KK) * 32 + vg;
        *(float4*)&g_yslot[gy]     = make_float4(y[0], y[1], y[2], y[3]);
        *(float4*)&g_yslot[gy + 4] = make_float4(y[4], y[5], y[6], y[7]);
    }

    {
        int n = tid >> 3, vg = (tid & 7) * 4;
        float u[4] = {0.f, 0.f, 0.f, 0.f};
#pragma unroll 4
        for (int s = 0; s < 64; s++) {
            float kd = ksT[n][s] * rr[s];
            float4 vv = *(const float4*)&vs[s][vg];
            u[0] = fmaf(kd, vv.x, u[0]); u[1] = fmaf(kd, vv.y, u[1]);
            u[2] = fmaf(kd, vv.z, u[2]); u[3] = fmaf(kd, vv.w, u[3]);
        }
        *(float4*)&g_U[(size_t)cid * 1024 + n * 32 + vg] = make_float4(u[0], u[1], u[2], u[3]);
    }
    if (tid == 0) g_P63[cid] = __expf(Ls[63]);
}

// ---------------- kernel: chunked scan phase 2 (state propagation) ----------------
__global__ void chunk_state(const float* __restrict__ S0,
                            float* __restrict__ sfin) {
    int tid = threadIdx.x;
    int seq = blockIdx.x;
    float S = S0[(size_t)seq * 1024 + tid];
#pragma unroll 1
    for (int c = 0; c < NCH; c++) {
        int cid = seq * NCH + c;
        g_Schunk[(size_t)cid * 1024 + tid] = S;
        float P = g_P63[cid];
        S = fmaf(P, S, g_U[(size_t)cid * 1024 + tid]);
    }
    if (sfin) sfin[(size_t)seq * 1024 + tid] = S;
}

// ---------------- kernel: chunked scan phase 3 (cross-chunk term) ----------------
__global__ void chunk_cross() {
    __shared__ float Sc[1024];
    __shared__ float qds[64][33];
    int tid = threadIdx.x;
    int cid = blockIdx.x;
    int b = cid >> 8, kk = (cid >> 5) & 7, c = cid & 31;
    size_t e0 = ((size_t)(b * TT + c * CC)) * KK + kk;

    {
        float4 s4 = *(const float4*)&g_Schunk[(size_t)cid * 1024 + tid * 4];
        *(float4*)&Sc[tid * 4] = s4;
    }
#pragma unroll
    for (int it = 0; it < 2; it++) {
        int i = (tid >> 3) + it * 32;
        int c4 = (tid & 7) * 4;
        float4 qv = *(const float4*)&g_qsel[(e0 + (size_t)i * KK) * 32 + c4];
        qds[i][c4] = qv.x; qds[i][c4+1] = qv.y; qds[i][c4+2] = qv.z; qds[i][c4+3] = qv.w;
    }
    __syncthreads();

    int i = tid >> 2, vg = (tid & 3) * 8;
    size_t gy = (e0 + (size_t)i * KK) * 32 + vg;
    float4 y0 = *(const float4*)&g_yslot[gy];
    float4 y1 = *(const float4*)&g_yslot[gy + 4];
    float y[8] = {y0.x, y0.y, y0.z, y0.w, y1.x, y1.y, y1.z, y1.w};
#pragma unroll 8
    for (int n = 0; n < 32; n++) {
        float qv = qds[i][n];
#pragma unroll
        for (int j = 0; j < 8; j++)
            y[j] = fmaf(qv, Sc[n * 32 + vg + j], y[j]);
    }
    *(float4*)&g_yslot[gy]     = make_float4(y[0], y[1], y[2], y[3]);
    *(float4*)&g_yslot[gy + 4] = make_float4(y[4], y[5], y[6], y[7]);
}

// ---------------- kernel: slot reduce -> g_ysum ----------------
__global__ void ysum_kernel() {
    int u = blockIdx.x * 256 + threadIdx.x;
    int t = u >> 5, v = u & 31;
    float s = 0.0f;
    size_t p = (size_t)t * KK * 32 + v;
#pragma unroll
    for (int kk = 0; kk < KK; kk++) s += g_yslot[p + kk * 32];
    g_ysum[u] = s;
}

// ---------------- kernel: output projection ----------------
__global__ void outproj_kernel(float* __restrict__ out) {
    __shared__ float ysum[32][32];
    int tid = threadIdx.x;
    int tok0 = blockIdx.x * 32;
    int d = blockIdx.y * 256 + tid;

#pragma unroll
    for (int u = tid; u < 1024; u += 256) {
        int tk = u >> 5, v = u & 31;
        ysum[tk][v] = g_ysum[(size_t)(tok0) * 32 + u];
    }
    __syncthreads();

    float wreg[32];
#pragma unroll
    for (int vv = 0; vv < 32; vv++) wreg[vv] = g_WoT[vv * DD + d];

#pragma unroll 4
    for (int tk = 0; tk < 32; tk++) {
        float acc = 0.0f;
#pragma unroll
        for (int vv = 0; vv < 32; vv += 4) {
            float4 y4 = *(const float4*)&ysum[tk][vv];
            acc = fmaf(wreg[vv],     y4.x, acc);
            acc = fmaf(wreg[vv + 1], y4.y, acc);
            acc = fmaf(wreg[vv + 2], y4.z, acc);
            acc = fmaf(wreg[vv + 3], y4.w, acc);
        }
        out[(size_t)(tok0 + tk) * DD + d] = acc;
    }
}

// ---------------- launch ----------------
extern "C" void kernel_launch(void* const* d_in, const int* in_sizes, int n_in,
                              void* d_out, int out_size) {
    const float* x       = (const float*)d_in[0];
    const float* Wr      = (const float*)d_in[1];
    const float* Wq      = (const float*)d_in[2];
    const float* Wk      = (const float*)d_in[3];
    const float* Wv      = (const float*)d_in[4];
    const float* Wa      = (const float*)d_in[5];
    const float* A_log   = (const float*)d_in[6];
    const float* dt_bias = (const float*)d_in[7];
    const float* Wo      = (const float*)d_in[8];
    const float* S0      = (const float*)d_in[9];
    float* out = (float*)d_out;

    const long y_elems = (long)NT * DD;
    const long s_elems = (long)BB * KK * NSd * HVd;
    float* sfin = ((long)out_size >= y_elems + s_elems) ? (out + y_elems) : nullptr;

    prep_kernel<<<7360, 256>>>(Wo, x, Wq, Wk, Wv, Wr, Wa);
    gemm_ra_f16<<<NT / 64, 256>>>(nullptr);
    route_kernel<<<NT / 16, 256>>>(A_log, dt_bias);
    gemm_qkv_f16<<<dim3(QTILES, HH), 256>>>(nullptr);
    chunk_intra<<<NCHUNKS, 256>>>();
    chunk_state<<<BB * KK, 1024>>>(S0, sfin);
    chunk_cross<<<NCHUNKS, 256>>>();
    ysum_kernel<<<NT * 32 / 256, 256>>>();
    outproj_kernel<<<dim3(NT / 32, 4), 256>>>(out);
}